// round 15
// baseline (speedup 1.0000x reference)
#include <cuda_runtime.h>
#include <math.h>
#include <stdint.h>

#define BB 4
#define TT 1024
#define CC 1024
#define HH 16
#define DD 64
#define NE 4194304     // B*T*C
#define LOG_DECAY (-0.6065306597126334f)
#define GN_EPS 64e-5f

typedef unsigned long long u64;

// ---------------- static scratch ----------------
__device__ float gScratch[104857600];

#define OO4  ((size_t)0)               // scan partials (slots 0-3)
#define OXR  ((size_t)0*NE)
#define OXK  ((size_t)2*NE)
#define OXV  ((size_t)3*NE)
#define OXC  ((size_t)4*NE)            // [x | xx] (slots 4-5)
#define ORB  ((size_t)6*NE)
#define OKB  ((size_t)7*NE)
#define OVB  ((size_t)8*NE)
#define OAB  ((size_t)9*NE)
#define OGB  ((size_t)10*NE)
#define OWL  ((size_t)11*NE)
#define OVMX ((size_t)12*NE)
#define OHST ((size_t)13*NE)
#define OHLO ((size_t)14*NE)           // dead after hsum_act -> reused as MA
#define OHHI ((size_t)15*NE)           // dead after hsum_act -> reused as BG
#define OMA  OHLO
#define OBG  OHHI
#define OEW  ((size_t)16*NE)
#define OBBA ((size_t)17*NE)
#define OKK2 ((size_t)19*NE)
#define OVVA ((size_t)20*NE)
#define OZB  ((size_t)21*NE)
#define OW2T ((size_t)22*NE)
#define OA2T (OW2T + 65536)
#define OV2T (OA2T + 65536)
#define OG2T (OV2T + 32768)
#define OWRr (OG2T + 131072)
#define OWKr (OWRr + 1048576)
#define OWVr (OWKr + 1048576)
#define OWOr (OWVr + 1048576)
#define OBU  (OWOr + 1048576)

__device__ __forceinline__ float to_tf32(float x){
    uint32_t u; asm("cvt.rna.tf32.f32 %0, %1;" : "=r"(u) : "f"(x));
    return __uint_as_float(u);
}
__device__ __forceinline__ float sigm_(float x){ return 1.f/(1.f+expf(-x)); }

__device__ __forceinline__ void mma8(float* d, const uint32_t* a, const uint32_t* b){
    asm volatile("mma.sync.aligned.m16n8k8.row.col.f32.tf32.tf32.f32 "
        "{%0,%1,%2,%3}, {%4,%5,%6,%7}, {%8,%9}, {%0,%1,%2,%3};"
        : "+f"(d[0]), "+f"(d[1]), "+f"(d[2]), "+f"(d[3])
        : "r"(a[0]), "r"(a[1]), "r"(a[2]), "r"(a[3]), "r"(b[0]), "r"(b[1]));
}
__device__ __forceinline__ void ldsm4(uint32_t* r, uint32_t a){
    asm volatile("ldmatrix.sync.aligned.m8n8.x4.shared.b16 {%0,%1,%2,%3}, [%4];"
        : "=r"(r[0]),"=r"(r[1]),"=r"(r[2]),"=r"(r[3]) : "r"(a));
}
__device__ __forceinline__ int swz(int r, int c){
    return r*32 + (int)((((((unsigned)c>>2) ^ ((unsigned)r & 7u)) << 2)) | ((unsigned)c & 3u));
}

// f32x2 packed math helpers
__device__ __forceinline__ u64 FMA2(u64 a, u64 b, u64 c){
    u64 d; asm("fma.rn.f32x2 %0, %1, %2, %3;" : "=l"(d) : "l"(a), "l"(b), "l"(c)); return d;
}
__device__ __forceinline__ u64 MUL2(u64 a, u64 b){
    u64 d; asm("mul.rn.f32x2 %0, %1, %2;" : "=l"(d) : "l"(a), "l"(b)); return d;
}
__device__ __forceinline__ u64 PK2(float x){
    u64 d; asm("mov.b64 %0, {%1, %1};" : "=l"(d) : "f"(x)); return d;
}
__device__ __forceinline__ float HADD2(u64 d){
    float a, b; asm("mov.b64 {%0, %1}, %2;" : "=f"(a), "=f"(b) : "l"(d)); return a + b;
}

// ---------------- job descriptor for batched GEMM ----------------
struct GJob {
    const float* A; const float* B; float* C; const float* bias;
    int lda, ldb, ldc, N, K, mode; float scale; int round_out; int nrep; int ny;
};
struct GPack { GJob j[8]; };

// ---------------- tf32 GEMM: C = A * B^T, z-batched pack, pipelined n-rep, ny early-exit ----
template<int NT>
__global__ void __launch_bounds__(256,2) gemm_mma(GPack p)
{
    extern __shared__ float sm[];
    const int AS  = 128*32;
    const int STG = (128+NT)*32;
    const int NTN = (NT==128) ? 8 : 4;
    const int NLD = NTN/2;

    GJob jb = p.j[blockIdx.z];
    if ((int)blockIdx.y >= jb.ny) return;

    int tid = threadIdx.x, wid = tid >> 5, lane = tid & 31;
    int bm0 = blockIdx.x * 128;
    int grp = lane >> 2, thr = lane & 3;
    int wm = (wid & 3) * 32;
    int wn = (NT==128) ? (wid >> 2) * 64 : (wid >> 2) * 32;
    int NC = jb.K >> 5;
    int total = jb.nrep * NC;
    int bnBase = blockIdx.y * jb.nrep;

    uint32_t smb = (uint32_t)__cvta_generic_to_shared(sm);

    uint32_t aoff[2][4], boff[NLD][4];
    #pragma unroll
    for (int mt=0;mt<2;mt++)
      #pragma unroll
      for (int kk=0;kk<4;kk++){
        int row = wm + mt*16 + (lane & 15);
        int col = kk*8 + (lane >> 4) * 4;
        aoff[mt][kk] = 4u * (uint32_t)swz(row, col);
      }
    #pragma unroll
    for (int np=0;np<NLD;np++)
      #pragma unroll
      for (int kk=0;kk<4;kk++){
        int row = wn + np*16 + (lane & 7) + ((lane >> 4) & 1) * 8;
        int col = kk*8 + ((lane >> 3) & 1) * 4;
        boff[np][kk] = 4u * (uint32_t)(AS + swz(row, col));
      }

    int ar = tid >> 3, aj = tid & 7;

    auto load_stage = [&](int stg, int rep, int c){
        const float* Ag = jb.A + (size_t)bm0 * jb.lda + c*32;
        #pragma unroll
        for (int i=0;i<4;i++){
            int r = ar + 32*i;
            unsigned dst = smb + 4u*(uint32_t)(stg*STG + swz(r, aj*4));
            const float* src = Ag + (size_t)r*jb.lda + aj*4;
            asm volatile("cp.async.ca.shared.global [%0], [%1], 16;"::"r"(dst),"l"(src));
        }
        int bn = (bnBase + rep) * NT;
        const float* Bg = jb.B + (size_t)bn * jb.ldb + c*32;
        #pragma unroll
        for (int i=0;i<NT/32;i++){
            int r = ar + 32*i;
            unsigned dst = smb + 4u*(uint32_t)(stg*STG + AS + swz(r, aj*4));
            const float* src = Bg + (size_t)r*jb.ldb + aj*4;
            asm volatile("cp.async.ca.shared.global [%0], [%1], 16;"::"r"(dst),"l"(src));
        }
    };

    float acc[2][NTN][4];
    #pragma unroll
    for (int i=0;i<2;i++)
      #pragma unroll
      for (int j=0;j<NTN;j++)
        #pragma unroll
        for (int l=0;l<4;l++) acc[i][j][l]=0.f;

    int pr = 0, pc = 0;
    load_stage(0, pr, pc);
    if (++pc == NC){ pc = 0; ++pr; }
    asm volatile("cp.async.commit_group;");
    if (total > 1){
        load_stage(1, pr, pc);
        if (++pc == NC){ pc = 0; ++pr; }
    }
    asm volatile("cp.async.commit_group;");

    int cstg = 0, pstg = 2;
    int cc = 0, erep = 0;
    for (int tc = 0; tc < total; tc++){
        asm volatile("cp.async.wait_group 1;");
        __syncthreads();
        uint32_t sb = smb + 4u*(uint32_t)(cstg * STG);
        #pragma unroll
        for (int kk=0; kk<4; kk++){
            uint32_t af[2][4];
            ldsm4(af[0], sb + aoff[0][kk]);
            ldsm4(af[1], sb + aoff[1][kk]);
            uint32_t bf[NLD][4];
            #pragma unroll
            for (int np=0;np<NLD;np++) ldsm4(bf[np], sb + boff[np][kk]);
            #pragma unroll
            for (int mt=0;mt<2;mt++)
                #pragma unroll
                for (int nt=0;nt<NTN;nt++)
                    mma8(acc[mt][nt], af[mt], &bf[nt>>1][(nt&1)*2]);
        }
        if (tc + 2 < total){
            load_stage(pstg, pr, pc);
            if (++pc == NC){ pc = 0; ++pr; }
        }
        asm volatile("cp.async.commit_group;");
        if (++cstg == 3) cstg = 0;
        if (++pstg == 3) pstg = 0;

        if (++cc == NC){
            cc = 0;
            int bn0 = (bnBase + erep) * NT;
            ++erep;
            #pragma unroll
            for (int mt=0;mt<2;mt++){
                #pragma unroll
                for (int nt=0;nt<NTN;nt++){
                    #pragma unroll
                    for (int half=0; half<2; half++){
                        int row = bm0 + wm + mt*16 + grp + half*8;
                        int col = bn0 + wn + nt*8 + thr*2;
                        float v0 = acc[mt][nt][half*2+0];
                        float v1 = acc[mt][nt][half*2+1];
                        if (jb.bias){ v0 += jb.bias[col]; v1 += jb.bias[col+1]; }
                        if (jb.mode==1){ v0 = tanhf(v0); v1 = tanhf(v1); }
                        else if (jb.mode==2){ v0 = jb.scale*sigm_(v0); v1 = jb.scale*sigm_(v1); }
                        else if (jb.mode==3){
                            v0 = (col   < 64) ? tanhf(v0) : (col   < 192 ? v0 : sigm_(v0));
                            v1 = (col+1 < 64) ? tanhf(v1) : (col+1 < 192 ? v1 : sigm_(v1));
                        }
                        if (jb.round_out){ v0 = to_tf32(v0); v1 = to_tf32(v1); }
                        float* cp = jb.C + (size_t)row*jb.ldc + col;
                        cp[0] = v0; cp[1] = v1;
                        acc[mt][nt][half*2+0] = 0.f;
                        acc[mt][nt][half*2+1] = 0.f;
                    }
                }
            }
        }
    }
}

// ---------------- fused elementwise prep: weights(vec4) + BU + transposes + mix ----------------
__device__ __forceinline__ void do_tr(const float* src, float* dst, int rows, int cols, int li){
    int r = li / cols, c = li - r * cols;
    dst[(size_t)c * rows + r] = to_tf32(src[li]);
}
__global__ __launch_bounds__(256) void elem_prep(
    const float* __restrict__ Wr, const float* __restrict__ Wk,
    const float* __restrict__ Wv, const float* __restrict__ Wo,
    const float* __restrict__ w1, const float* __restrict__ a1,
    const float* __restrict__ v1, const float* __restrict__ g1,
    const float* __restrict__ w2, const float* __restrict__ a2,
    const float* __restrict__ v2, const float* __restrict__ g2,
    const float* __restrict__ x_w, const float* __restrict__ x_a,
    const float* __restrict__ x_v, const float* __restrict__ x_g,
    const float* __restrict__ x,
    const float* __restrict__ mr, const float* __restrict__ mk, const float* __restrict__ mv,
    float* __restrict__ Sg)
{
    int bx = blockIdx.x;
    if (bx < 4096){
        int idx = bx * 256 + threadIdx.x;
        int m = idx >> 18;
        int i = idx & 262143;
        const float* src = (m == 0) ? Wr : (m == 1) ? Wk : (m == 2) ? Wv : Wo;
        float* dst = Sg + ((m == 0) ? OWRr : (m == 1) ? OWKr : (m == 2) ? OWVr : OWOr);
        float4 v = ((const float4*)src)[i];
        ((float4*)dst)[i] = make_float4(to_tf32(v.x), to_tf32(v.y), to_tf32(v.z), to_tf32(v.w));
        return;
    }
    bx -= 4096;
    if (bx < 2560){
        int idx = bx * 256 + threadIdx.x;
        int n = idx >> 11;
        int k = idx & 2047;
        int kk = k & 1023;
        float val = 0.f;
        if (n < 64){
            float w = w1[kk*64 + n];
            val = (k < 1024) ? w : x_w[kk]*w;
        } else if (n < 128){
            float w = a1[kk*64 + (n-64)];
            val = (k < 1024) ? w : x_a[kk]*w;
        } else if (n < 160){
            float w = v1[kk*32 + (n-128)];
            val = (k < 1024) ? w : x_v[kk]*w;
        } else if (n >= 192){
            float w = g1[kk*128 + (n-192)];
            val = (k < 1024) ? w : x_g[kk]*w;
        }
        Sg[OBU + idx] = to_tf32(val);
        return;
    }
    bx -= 2560;
    if (bx < 1152){
        int j = bx * 256 + threadIdx.x;
        if (j >= 294912) return;
        if      (j < 65536 )  do_tr(w2, Sg+OW2T, 64, 1024,  j);
        else if (j < 131072)  do_tr(a2, Sg+OA2T, 64, 1024,  j-65536);
        else if (j < 163840)  do_tr(v2, Sg+OV2T, 32, 1024,  j-131072);
        else                  do_tr(g2, Sg+OG2T, 128, 1024, j-163840);
        return;
    }
    bx -= 1152;
    {
        int row = bx;
        int t = row & (TT-1);
        int c4 = threadIdx.x;
        const float4* xv4 = (const float4*)x;
        float4 xc = xv4[(size_t)row*256 + c4];
        float4 xp = make_float4(0.f,0.f,0.f,0.f);
        if (t > 0) xp = xv4[(size_t)(row-1)*256 + c4];
        float4 dx = make_float4(xp.x-xc.x, xp.y-xc.y, xp.z-xc.z, xp.w-xc.w);
        size_t o = (size_t)row*256 + c4;
        float4 m;
        #define MIXOUT(dst, mp) \
            m = ((const float4*)mp)[c4]; \
            ((float4*)(Sg+dst))[o] = make_float4(to_tf32(xc.x+dx.x*m.x), to_tf32(xc.y+dx.y*m.y), \
                                                 to_tf32(xc.z+dx.z*m.z), to_tf32(xc.w+dx.w*m.w));
        MIXOUT(OXR, mr) MIXOUT(OXK, mk) MIXOUT(OXV, mv)
        #undef MIXOUT
        float4* xcp = (float4*)(Sg + OXC + (size_t)row*2048);
        xcp[c4]       = make_float4(to_tf32(xc.x), to_tf32(xc.y), to_tf32(xc.z), to_tf32(xc.w));
        xcp[256 + c4] = make_float4(to_tf32(dx.x), to_tf32(dx.y), to_tf32(dx.z), to_tf32(dx.w));
    }
}

// ---------------- H = act(Hlo + Hhi) ----------------
__global__ __launch_bounds__(256) void hsum_act(
    const float* __restrict__ Hlo, const float* __restrict__ Hhi, float* __restrict__ H)
{
    int i = blockIdx.x*256 + threadIdx.x;
    if (i >= 4096*80) return;
    int row = i / 80, q = i - row*80;
    int col = q*4;
    size_t off = (size_t)row*320 + col;
    float4 a = *(const float4*)&Hlo[off];
    float4 b = *(const float4*)&Hhi[off];
    float v[4] = {a.x+b.x, a.y+b.y, a.z+b.z, a.w+b.w};
    #pragma unroll
    for (int j=0;j<4;j++){
        int c = col + j;
        float xx = v[j];
        xx = (c < 64) ? tanhf(xx) : (c < 192 ? xx : sigm_(xx));
        v[j] = to_tf32(xx);
    }
    *(float4*)&H[off] = make_float4(v[0], v[1], v[2], v[3]);
}

// ---------------- scan-operand prep (with fused look-ahead MA/BG) ----------------
__global__ __launch_bounds__(256) void prep_kernel(
    const float* __restrict__ K, const float* __restrict__ A, const float* __restrict__ V,
    const float* __restrict__ WL, const float* __restrict__ VMIX, const float* __restrict__ vfirst,
    const float* __restrict__ k_k, const float* __restrict__ k_a,
    float* __restrict__ EW, float* __restrict__ BBo,
    float* __restrict__ K2o, float* __restrict__ Vo,
    float* __restrict__ MA, float* __restrict__ BG)
{
    int gw = (blockIdx.x*256 + threadIdx.x) >> 5;
    int lane = threadIdx.x & 31;
    int h = gw & 15, t = (gw >> 4) & 1023, b = gw >> 14;
    int c = h*64 + lane*2;
    size_t btc = ((size_t)(b*TT + t))*CC + c;
    float2 k  = *(const float2*)&K[btc];
    float2 kw = *(const float2*)&k_k[c];
    float2 ka = *(const float2*)&k_a[c];
    float2 a  = *(const float2*)&A[btc];
    float kk0 = k.x*kw.x, kk1 = k.y*kw.y;
    float2 kn = make_float2(0.f, 0.f);
    if (t < TT-1) kn = *(const float2*)&K[btc + CC];
    float kn0 = kn.x*kw.x, kn1 = kn.y*kw.y;
    float ss  = kk0*kk0 + kk1*kk1;
    float ssn = kn0*kn0 + kn1*kn1;
    #pragma unroll
    for (int off=16; off>0; off>>=1){
        ss  += __shfl_xor_sync(0xffffffffu, ss, off);
        ssn += __shfl_xor_sync(0xffffffffu, ssn, off);
    }
    float inv  = 1.f / fmaxf(sqrtf(ss), 1e-12f);
    float invn = 1.f / fmaxf(sqrtf(ssn), 1e-12f);
    kk0 *= inv; kk1 *= inv;
    float aan0 = -kn0*invn, aan1 = -kn1*invn;

    float2 wl = *(const float2*)&WL[btc];
    float2 v  = *(const float2*)&V[btc];
    float2 vf = *(const float2*)&vfirst[btc];
    float2 vm = *(const float2*)&VMIX[btc];
    v.x = v.x + (vf.x - v.x)*vm.x;
    v.y = v.y + (vf.y - v.y)*vm.y;
    float k20 = k.x*(1.f + (a.x-1.f)*ka.x);
    float k21 = k.y*(1.f + (a.y-1.f)*ka.y);
    float ew0 = expf(wl.x), ew1 = expf(wl.y);
    float bb0 = kk0*a.x, bb1 = kk1*a.y;

    float bsum = bb0*aan0 + bb1*aan1;
    float gsum = k20*aan0 + k21*aan1;
    #pragma unroll
    for (int off=16; off>0; off>>=1){
        bsum += __shfl_xor_sync(0xffffffffu, bsum, off);
        gsum += __shfl_xor_sync(0xffffffffu, gsum, off);
    }

    size_t bhtd = ((size_t)((b*HH + h)*TT + t))*64 + lane*2;
    *(float2*)&EW[bhtd]  = make_float2(ew0, ew1);
    *(float2*)&BBo[bhtd] = make_float2(bb0, bb1);
    *(float2*)&K2o[bhtd] = make_float2(k20, k21);
    *(float2*)&Vo[bhtd]  = v;
    *(float2*)&MA[bhtd]  = make_float2(ew0*aan0, ew1*aan1);
    if (lane == 0)
        *(float2*)&BG[((size_t)(b*HH + h)*TT + t)*2] = make_float2(bsum, gsum);
}

// ---------------- scan v4: look-ahead recurrence, 128 thr, 4 rows x 4 cols ----------------
__global__ void __launch_bounds__(128) scan_kernel(
    const float* __restrict__ EW, const float* __restrict__ BBp, const float* __restrict__ MAp,
    const float* __restrict__ K2p, const float* __restrict__ RB, const float* __restrict__ Vp,
    const float* __restrict__ BG, float* __restrict__ O4)
{
    __shared__ float sm[16*6*64];
    __shared__ float bg_sm[32];
    int bh = blockIdx.x >> 1;
    int b = bh >> 4, h = bh & 15;
    int rowBase = (blockIdx.x & 1) * 32;
    int tid = threadIdx.x;
    int cg = tid & 15;
    int rg = tid >> 4;
    int col0 = cg * 4;
    size_t base = (size_t)bh * TT * 64;
    size_t base4 = (size_t)bh * TT * 256;
    const float* BGp = BG + (size_t)bh * TT * 2;

    const float* mysrc = nullptr; int mystride = 64;
    int arr = tid >> 4, seg = tid & 15;
    if (tid < 96){
        switch (arr){
            case 0: mysrc = EW  + base; break;
            case 1: mysrc = BBp + base; break;
            case 2: mysrc = MAp + base; break;
            case 3: mysrc = K2p + base; break;
            case 4: mysrc = RB + (size_t)b*TT*CC + h*64; mystride = CC; break;
            case 5: mysrc = Vp  + base; break;
        }
    }
    uint32_t smb = (uint32_t)__cvta_generic_to_shared(sm);
    uint32_t smbg = (uint32_t)__cvta_generic_to_shared(bg_sm);

    auto pf4 = [&](int batch){
        if (tid < 96){
            #pragma unroll
            for (int u=0; u<4; u++){
                int t = batch*4 + u;
                const float* g = mysrc + (size_t)t*mystride + seg*4;
                unsigned sa = smb + 4u*(uint32_t)(((t&15)*384) + arr*64 + seg*4);
                asm volatile("cp.async.ca.shared.global [%0], [%1], 16;"::"r"(sa),"l"(g));
            }
        } else if (tid < 98){
            const float* g = BGp + (size_t)batch*8 + (tid-96)*4;
            unsigned sa = smbg + 4u*(uint32_t)((((batch*4)&15)*2) + (tid-96)*4);
            asm volatile("cp.async.ca.shared.global [%0], [%1], 16;"::"r"(sa),"l"(g));
        }
        asm volatile("cp.async.commit_group;");
    };

    pf4(0); pf4(1); pf4(2);

    u64 S2[4][2];
    float sab[4];
    #pragma unroll
    for (int j=0;j<4;j++){ S2[j][0]=0ull; S2[j][1]=0ull; sab[j]=0.f; }

    for (int i=0; i<256; i++){
        asm volatile("cp.async.wait_group 2;");
        __syncthreads();
        if (i+3 < 256) pf4(i+3);
        else asm volatile("cp.async.commit_group;");
        int tb = i*4;

        #pragma unroll
        for (int u=0; u<4; u++){
            const float* st = &sm[((tb+u) & 15) * 384];
            u64 ew2[2], bb2[2], ma2[2], kk2[2], rr2[2];
            #define LD2(dst, off) { \
                ulonglong2 q = *(const ulonglong2*)&st[(off)+col0]; \
                dst[0]=q.x; dst[1]=q.y; }
            LD2(ew2,   0) LD2(bb2,  64) LD2(ma2, 128) LD2(kk2, 192) LD2(rr2, 256)
            #undef LD2
            float vv[4];
            #pragma unroll
            for (int j=0;j<4;j++) vv[j] = st[320 + rowBase + rg + 8*j];
            float2 bg = *(const float2*)&bg_sm[((tb+u)&15)*2];

            float Dp[4];
            #pragma unroll
            for (int j=0;j<4;j++)
                Dp[j] = HADD2(FMA2(S2[j][1], ma2[1], MUL2(S2[j][0], ma2[0])));
            #pragma unroll
            for (int j=0;j<4;j++){
                Dp[j] += __shfl_xor_sync(0xffffffffu, Dp[j], 1);
                Dp[j] += __shfl_xor_sync(0xffffffffu, Dp[j], 2);
                Dp[j] += __shfl_xor_sync(0xffffffffu, Dp[j], 4);
                Dp[j] += __shfl_xor_sync(0xffffffffu, Dp[j], 8);
            }

            float po[4];
            #pragma unroll
            for (int j=0;j<4;j++){
                u64 sab2 = PK2(sab[j]), vv2 = PK2(vv[j]);
                S2[j][0] = FMA2(kk2[0], vv2, FMA2(bb2[0], sab2, MUL2(S2[j][0], ew2[0])));
                S2[j][1] = FMA2(kk2[1], vv2, FMA2(bb2[1], sab2, MUL2(S2[j][1], ew2[1])));
                po[j] = HADD2(FMA2(S2[j][1], rr2[1], MUL2(S2[j][0], rr2[0])));
                po[j] += __shfl_xor_sync(0xffffffffu, po[j], 1);
                po[j] += __shfl_xor_sync(0xffffffffu, po[j], 2);
            }
            #pragma unroll
            for (int j=0;j<4;j++)
                sab[j] = Dp[j] + sab[j]*bg.x + vv[j]*bg.y;

            if ((tid & 3) == 0){
                size_t ob = base4 + (size_t)(tb+u)*256;
                int p = cg >> 2;
                #pragma unroll
                for (int j=0;j<4;j++)
                    O4[ob + (size_t)(rowBase + rg + 8*j)*4 + p] = po[j];
            }
        }
    }
}

// ---------------- post: sum partials + groupnorm + bonus + gate ----------------
__global__ __launch_bounds__(256) void post_kernel(
    const float* __restrict__ O4, const float* __restrict__ RB, const float* __restrict__ K2p,
    const float* __restrict__ Vp, const float* __restrict__ G,
    const float* __restrict__ r_k, const float* __restrict__ gn_w, const float* __restrict__ gn_b,
    float* __restrict__ Z)
{
    int gw = (blockIdx.x*256 + threadIdx.x) >> 5;
    int lane = threadIdx.x & 31;
    int h = gw & 15, t = (gw >> 4) & 1023, b = gw >> 14;
    size_t bhtd = ((size_t)((b*HH + h)*TT + t))*64 + lane*2;
    int c = h*64 + lane*2;
    size_t btc = ((size_t)(b*TT + t))*CC + c;

    size_t b4 = ((size_t)(b*HH + h))*TT*256 + (size_t)t*256 + (size_t)lane*8;
    float4 pa = *(const float4*)&O4[b4];
    float4 pb = *(const float4*)&O4[b4 + 4];
    float2 o = make_float2(pa.x+pa.y+pa.z+pa.w, pb.x+pb.y+pb.z+pb.w);

    float sm = o.x + o.y;
    #pragma unroll
    for (int off=16; off>0; off>>=1) sm += __shfl_xor_sync(0xffffffffu, sm, off);
    float mean = sm * (1.f/64.f);
    float dx = o.x - mean, dy = o.y - mean;
    float vs = dx*dx + dy*dy;
    #pragma unroll
    for (int off=16; off>0; off>>=1) vs += __shfl_xor_sync(0xffffffffu, vs, off);
    float inv = rsqrtf(vs*(1.f/64.f) + GN_EPS);

    float2 r  = *(const float2*)&RB[btc];
    float2 k2 = *(const float2*)&K2p[bhtd];
    float2 v  = *(const float2*)&Vp[bhtd];
    float2 rk = *(const float2*)&r_k[c];
    float bs = r.x*k2.x*rk.x + r.y*k2.y*rk.y;
    #pragma unroll
    for (int off=16; off>0; off>>=1) bs += __shfl_xor_sync(0xffffffffu, bs, off);

    float2 g  = *(const float2*)&G[btc];
    float2 w  = *(const float2*)&gn_w[c];
    float2 bb = *(const float2*)&gn_b[c];
    float z0 = ((dx*inv)*w.x + bb.x + bs*v.x) * g.x;
    float z1 = ((dy*inv)*w.y + bb.y + bs*v.y) * g.y;
    *(float2*)&Z[btc] = make_float2(to_tf32(z0), to_tf32(z1));
}

// ---------------- driver ----------------
static inline GJob mkjob(const float* A, int lda, const float* B, int ldb, float* C, int ldc,
                         int N, int K, const float* bias, int mode, float scale, int ro,
                         int nrep, int ny){
    GJob j; j.A=A; j.B=B; j.C=C; j.bias=bias; j.lda=lda; j.ldb=ldb; j.ldc=ldc;
    j.N=N; j.K=K; j.mode=mode; j.scale=scale; j.round_out=ro; j.nrep=nrep; j.ny=ny; return j;
}

extern "C" void kernel_launch(void* const* d_in, const int* in_sizes, int n_in,
                              void* d_out, int out_size) {
    const float* x   = (const float*)d_in[0];
    const float* vfi = (const float*)d_in[1];
    const float* x_r = (const float*)d_in[2];
    const float* x_w = (const float*)d_in[3];
    const float* x_k = (const float*)d_in[4];
    const float* x_v = (const float*)d_in[5];
    const float* x_a = (const float*)d_in[6];
    const float* x_g = (const float*)d_in[7];
    const float* Wr  = (const float*)d_in[8];
    const float* Wk  = (const float*)d_in[9];
    const float* Wv  = (const float*)d_in[10];
    const float* Wo  = (const float*)d_in[11];
    const float* w0  = (const float*)d_in[12];
    const float* w1  = (const float*)d_in[13];
    const float* w2  = (const float*)d_in[14];
    const float* a0  = (const float*)d_in[15];
    const float* a1  = (const float*)d_in[16];
    const float* a2  = (const float*)d_in[17];
    const float* v0  = (const float*)d_in[18];
    const float* v1  = (const float*)d_in[19];
    const float* v2  = (const float*)d_in[20];
    const float* g1  = (const float*)d_in[21];
    const float* g2  = (const float*)d_in[22];
    const float* k_k = (const float*)d_in[23];
    const float* k_a = (const float*)d_in[24];
    const float* r_k = (const float*)d_in[25];
    const float* gnw = (const float*)d_in[26];
    const float* gnb = (const float*)d_in[27];
    float* out = (float*)d_out;

    float* S;
    cudaGetSymbolAddress((void**)&S, gScratch);

    const int SM128 = 3*(128+128)*32*4;   // 98304
    const int SM64  = 3*(128+64)*32*4;    // 73728
    cudaFuncSetAttribute(gemm_mma<128>, cudaFuncAttributeMaxDynamicSharedMemorySize, SM128);
    cudaFuncSetAttribute(gemm_mma<64>,  cudaFuncAttributeMaxDynamicSharedMemorySize, SM64);

    const int M = BB*TT;
    float* H = S + OHST;

    // 0: fused elementwise prep
    elem_prep<<<4096+2560+1152+4096, 256>>>(Wr, Wk, Wv, Wo, w1, a1, v1, g1, w2, a2, v2, g2,
                                            x_w, x_a, x_v, x_g, x, x_r, x_k, x_v, S);
    // 1: stage-1 split-K halves
    {
        GPack p{};
        p.j[0] = mkjob(S+OXC,      2048, S+OBU,      2048, S+OHLO, 320, 320, 1024, nullptr, 0, 1.f, 0, 1, 5);
        p.j[1] = mkjob(S+OXC+1024, 2048, S+OBU+1024, 2048, S+OHHI, 320, 320, 1024, nullptr, 0, 1.f, 0, 1, 5);
        gemm_mma<64><<<dim3(M/128,5,2), 256, SM64>>>(p);
    }
    // 2: H = act(Hlo + Hhi)
    hsum_act<<<1280, 256>>>(S+OHLO, S+OHHI, H);
    // 3: MERGED: R/K/V projections + stage-2 low-rank outputs (7 jobs)  <-- profiled (idx 3)
    {
        GPack p{};
        p.j[0] = mkjob(S+OXR, 1024, S+OWRr, 1024, S+ORB, 1024, 1024, 1024, nullptr, 0, 1.f, 0, 1, 8);
        p.j[1] = mkjob(S+OXK, 1024, S+OWKr, 1024, S+OKB, 1024, 1024, 1024, nullptr, 0, 1.f, 0, 1, 8);
        p.j[2] = mkjob(S+OXV, 1024, S+OWVr, 1024, S+OVB, 1024, 1024, 1024, nullptr, 0, 1.f, 0, 1, 8);
        p.j[3] = mkjob(H+0,   320, S+OW2T, 64,  S+OWL,  1024, 1024, 64,  w0, 2, LOG_DECAY, 0, 4, 2);
        p.j[4] = mkjob(H+64,  320, S+OA2T, 64,  S+OAB,  1024, 1024, 64,  a0, 2, 1.f, 0, 4, 2);
        p.j[5] = mkjob(H+128, 320, S+OV2T, 32,  S+OVMX, 1024, 1024, 32,  v0, 2, 1.f, 0, 4, 2);
        p.j[6] = mkjob(H+192, 320, S+OG2T, 128, S+OGB,  1024, 1024, 128, nullptr, 0, 1.f, 0, 4, 2);
        gemm_mma<128><<<dim3(M/128,8,7), 256, SM128>>>(p);
    }
    // 4: scan operand prep (fused look-ahead MA/BG)
    prep_kernel<<<(BB*TT*HH*32)/256, 256>>>(S+OKB, S+OAB, S+OVB, S+OWL, S+OVMX, vfi,
                                            k_k, k_a,
                                            S+OEW, S+OBBA, S+OKK2, S+OVVA, S+OMA, S+OBG);
    // 5: sequential scan v4 (128 CTAs, 32 rows each)
    scan_kernel<<<BB*HH*2, 128>>>(S+OEW, S+OBBA, S+OMA, S+OKK2, S+ORB, S+OVVA, S+OBG, S+OO4);
    // 6: sum partials + groupnorm + bonus + gate
    post_kernel<<<(BB*TT*HH*32)/256, 256>>>(S+OO4, S+ORB, S+OKK2, S+OVVA, S+OGB,
                                            r_k, gnw, gnb, S+OZB);
    // 7: out = Z @ Wo^T
    {
        GPack p{};
        p.j[0] = mkjob(S+OZB, 1024, S+OWOr, 1024, out, 1024, 1024, 1024, nullptr, 0, 1.f, 0, 1, 8);
        gemm_mma<128><<<dim3(M/128,8,1), 256, SM128>>>(p);
    }
    // v_first passthrough
    if (out_size >= 2*NE){
        cudaMemcpyAsync(out + NE, vfi, (size_t)NE*sizeof(float), cudaMemcpyDeviceToDevice);
    }
}

// round 16
// speedup vs baseline: 1.0399x; 1.0399x over previous
#include <cuda_runtime.h>
#include <math.h>
#include <stdint.h>

#define BB 4
#define TT 1024
#define CC 1024
#define HH 16
#define DD 64
#define NE 4194304     // B*T*C
#define LOG_DECAY (-0.6065306597126334f)
#define GN_EPS 64e-5f

typedef unsigned long long u64;

// ---------------- static scratch ----------------
__device__ float gScratch[104857600];

#define OO4  ((size_t)0)               // scan partials (slots 0-3)
#define OXR  ((size_t)0*NE)
#define OXK  ((size_t)2*NE)
#define OXV  ((size_t)3*NE)
#define OXC  ((size_t)4*NE)            // [x | xx] (slots 4-5)
#define ORB  ((size_t)6*NE)
#define OKB  ((size_t)7*NE)
#define OVB  ((size_t)8*NE)
#define OAB  ((size_t)9*NE)
#define OGB  ((size_t)10*NE)
#define OWL  ((size_t)11*NE)
#define OVMX ((size_t)12*NE)
#define OHST ((size_t)13*NE)
#define OHLO ((size_t)14*NE)           // dead after hsum_act -> reused as MA
#define OHHI ((size_t)15*NE)           // dead after hsum_act -> reused as BG
#define OMA  OHLO
#define OBG  OHHI
#define OEW  ((size_t)16*NE)
#define OBBA ((size_t)17*NE)
#define OKK2 ((size_t)19*NE)
#define OVVA ((size_t)20*NE)
#define OZB  ((size_t)21*NE)
#define OW2T ((size_t)22*NE)
#define OA2T (OW2T + 65536)
#define OV2T (OA2T + 65536)
#define OG2T (OV2T + 32768)
#define OWRr (OG2T + 131072)
#define OWKr (OWRr + 1048576)
#define OWVr (OWKr + 1048576)
#define OWOr (OWVr + 1048576)
#define OBU  (OWOr + 1048576)

__device__ __forceinline__ float to_tf32(float x){
    uint32_t u; asm("cvt.rna.tf32.f32 %0, %1;" : "=r"(u) : "f"(x));
    return __uint_as_float(u);
}
__device__ __forceinline__ float sigm_(float x){ return 1.f/(1.f+expf(-x)); }

__device__ __forceinline__ void mma8(float* d, const uint32_t* a, const uint32_t* b){
    asm volatile("mma.sync.aligned.m16n8k8.row.col.f32.tf32.tf32.f32 "
        "{%0,%1,%2,%3}, {%4,%5,%6,%7}, {%8,%9}, {%0,%1,%2,%3};"
        : "+f"(d[0]), "+f"(d[1]), "+f"(d[2]), "+f"(d[3])
        : "r"(a[0]), "r"(a[1]), "r"(a[2]), "r"(a[3]), "r"(b[0]), "r"(b[1]));
}
__device__ __forceinline__ void ldsm4(uint32_t* r, uint32_t a){
    asm volatile("ldmatrix.sync.aligned.m8n8.x4.shared.b16 {%0,%1,%2,%3}, [%4];"
        : "=r"(r[0]),"=r"(r[1]),"=r"(r[2]),"=r"(r[3]) : "r"(a));
}
__device__ __forceinline__ int swz(int r, int c){
    return r*32 + (int)((((((unsigned)c>>2) ^ ((unsigned)r & 7u)) << 2)) | ((unsigned)c & 3u));
}

// f32x2 packed math helpers
__device__ __forceinline__ u64 FMA2(u64 a, u64 b, u64 c){
    u64 d; asm("fma.rn.f32x2 %0, %1, %2, %3;" : "=l"(d) : "l"(a), "l"(b), "l"(c)); return d;
}
__device__ __forceinline__ u64 MUL2(u64 a, u64 b){
    u64 d; asm("mul.rn.f32x2 %0, %1, %2;" : "=l"(d) : "l"(a), "l"(b)); return d;
}
__device__ __forceinline__ u64 PK2(float x){
    u64 d; asm("mov.b64 %0, {%1, %1};" : "=l"(d) : "f"(x)); return d;
}
__device__ __forceinline__ float HADD2(u64 d){
    float a, b; asm("mov.b64 {%0, %1}, %2;" : "=f"(a), "=f"(b) : "l"(d)); return a + b;
}

// ---------------- job descriptor for batched GEMM ----------------
struct GJob {
    const float* A; const float* B; float* C; const float* bias;
    int lda, ldb, ldc, N, K, mode; float scale; int round_out; int nrep; int ny;
};
struct GPack { GJob j[8]; };

// ---------------- tf32 GEMM: C = A * B^T, z-batched pack, pipelined n-rep, ny early-exit ----
template<int NT>
__global__ void __launch_bounds__(256,2) gemm_mma(GPack p)
{
    extern __shared__ float sm[];
    const int AS  = 128*32;
    const int STG = (128+NT)*32;
    const int NTN = (NT==128) ? 8 : 4;
    const int NLD = NTN/2;

    GJob jb = p.j[blockIdx.z];
    if ((int)blockIdx.y >= jb.ny) return;

    int tid = threadIdx.x, wid = tid >> 5, lane = tid & 31;
    int bm0 = blockIdx.x * 128;
    int grp = lane >> 2, thr = lane & 3;
    int wm = (wid & 3) * 32;
    int wn = (NT==128) ? (wid >> 2) * 64 : (wid >> 2) * 32;
    int NC = jb.K >> 5;
    int total = jb.nrep * NC;
    int bnBase = blockIdx.y * jb.nrep;

    uint32_t smb = (uint32_t)__cvta_generic_to_shared(sm);

    uint32_t aoff[2][4], boff[NLD][4];
    #pragma unroll
    for (int mt=0;mt<2;mt++)
      #pragma unroll
      for (int kk=0;kk<4;kk++){
        int row = wm + mt*16 + (lane & 15);
        int col = kk*8 + (lane >> 4) * 4;
        aoff[mt][kk] = 4u * (uint32_t)swz(row, col);
      }
    #pragma unroll
    for (int np=0;np<NLD;np++)
      #pragma unroll
      for (int kk=0;kk<4;kk++){
        int row = wn + np*16 + (lane & 7) + ((lane >> 4) & 1) * 8;
        int col = kk*8 + ((lane >> 3) & 1) * 4;
        boff[np][kk] = 4u * (uint32_t)(AS + swz(row, col));
      }

    int ar = tid >> 3, aj = tid & 7;

    auto load_stage = [&](int stg, int rep, int c){
        const float* Ag = jb.A + (size_t)bm0 * jb.lda + c*32;
        #pragma unroll
        for (int i=0;i<4;i++){
            int r = ar + 32*i;
            unsigned dst = smb + 4u*(uint32_t)(stg*STG + swz(r, aj*4));
            const float* src = Ag + (size_t)r*jb.lda + aj*4;
            asm volatile("cp.async.cg.shared.global [%0], [%1], 16;"::"r"(dst),"l"(src));
        }
        int bn = (bnBase + rep) * NT;
        const float* Bg = jb.B + (size_t)bn * jb.ldb + c*32;
        #pragma unroll
        for (int i=0;i<NT/32;i++){
            int r = ar + 32*i;
            unsigned dst = smb + 4u*(uint32_t)(stg*STG + AS + swz(r, aj*4));
            const float* src = Bg + (size_t)r*jb.ldb + aj*4;
            asm volatile("cp.async.cg.shared.global [%0], [%1], 16;"::"r"(dst),"l"(src));
        }
    };

    float acc[2][NTN][4];
    #pragma unroll
    for (int i=0;i<2;i++)
      #pragma unroll
      for (int j=0;j<NTN;j++)
        #pragma unroll
        for (int l=0;l<4;l++) acc[i][j][l]=0.f;

    int pr = 0, pc = 0;
    load_stage(0, pr, pc);
    if (++pc == NC){ pc = 0; ++pr; }
    asm volatile("cp.async.commit_group;");
    if (total > 1){
        load_stage(1, pr, pc);
        if (++pc == NC){ pc = 0; ++pr; }
    }
    asm volatile("cp.async.commit_group;");

    int cstg = 0, pstg = 2;
    int cc = 0, erep = 0;
    uint32_t sb = smb;
    for (int tc = 0; tc < total; tc++){
        asm volatile("cp.async.wait_group 1;");
        __syncthreads();
        #pragma unroll
        for (int kk=0; kk<4; kk++){
            uint32_t af[2][4];
            ldsm4(af[0], sb + aoff[0][kk]);
            ldsm4(af[1], sb + aoff[1][kk]);
            uint32_t bf[NLD][4];
            #pragma unroll
            for (int np=0;np<NLD;np++) ldsm4(bf[np], sb + boff[np][kk]);
            #pragma unroll
            for (int mt=0;mt<2;mt++)
                #pragma unroll
                for (int nt=0;nt<NTN;nt++)
                    mma8(acc[mt][nt], af[mt], &bf[nt>>1][(nt&1)*2]);
        }
        if (tc + 2 < total){
            load_stage(pstg, pr, pc);
            if (++pc == NC){ pc = 0; ++pr; }
        }
        asm volatile("cp.async.commit_group;");
        if (++cstg == 3){ cstg = 0; sb = smb; } else sb += 4u*STG;
        if (++pstg == 3) pstg = 0;

        if (++cc == NC){
            cc = 0;
            int bn0 = (bnBase + erep) * NT;
            ++erep;
            #pragma unroll
            for (int mt=0;mt<2;mt++){
                #pragma unroll
                for (int nt=0;nt<NTN;nt++){
                    #pragma unroll
                    for (int half=0; half<2; half++){
                        int row = bm0 + wm + mt*16 + grp + half*8;
                        int col = bn0 + wn + nt*8 + thr*2;
                        float v0 = acc[mt][nt][half*2+0];
                        float v1 = acc[mt][nt][half*2+1];
                        if (jb.bias){ v0 += jb.bias[col]; v1 += jb.bias[col+1]; }
                        if (jb.mode==1){ v0 = tanhf(v0); v1 = tanhf(v1); }
                        else if (jb.mode==2){ v0 = jb.scale*sigm_(v0); v1 = jb.scale*sigm_(v1); }
                        else if (jb.mode==3){
                            v0 = (col   < 64) ? tanhf(v0) : (col   < 192 ? v0 : sigm_(v0));
                            v1 = (col+1 < 64) ? tanhf(v1) : (col+1 < 192 ? v1 : sigm_(v1));
                        }
                        if (jb.round_out){ v0 = to_tf32(v0); v1 = to_tf32(v1); }
                        float* cp = jb.C + (size_t)row*jb.ldc + col;
                        cp[0] = v0; cp[1] = v1;
                        acc[mt][nt][half*2+0] = 0.f;
                        acc[mt][nt][half*2+1] = 0.f;
                    }
                }
            }
        }
    }
}

// ---------------- fused elementwise prep: weights(vec4) + BU + transposes + mix ----------------
__device__ __forceinline__ void do_tr(const float* src, float* dst, int rows, int cols, int li){
    int r = li / cols, c = li - r * cols;
    dst[(size_t)c * rows + r] = to_tf32(src[li]);
}
__global__ __launch_bounds__(256) void elem_prep(
    const float* __restrict__ Wr, const float* __restrict__ Wk,
    const float* __restrict__ Wv, const float* __restrict__ Wo,
    const float* __restrict__ w1, const float* __restrict__ a1,
    const float* __restrict__ v1, const float* __restrict__ g1,
    const float* __restrict__ w2, const float* __restrict__ a2,
    const float* __restrict__ v2, const float* __restrict__ g2,
    const float* __restrict__ x_w, const float* __restrict__ x_a,
    const float* __restrict__ x_v, const float* __restrict__ x_g,
    const float* __restrict__ x,
    const float* __restrict__ mr, const float* __restrict__ mk, const float* __restrict__ mv,
    float* __restrict__ Sg)
{
    int bx = blockIdx.x;
    if (bx < 4096){
        int idx = bx * 256 + threadIdx.x;
        int m = idx >> 18;
        int i = idx & 262143;
        const float* src = (m == 0) ? Wr : (m == 1) ? Wk : (m == 2) ? Wv : Wo;
        float* dst = Sg + ((m == 0) ? OWRr : (m == 1) ? OWKr : (m == 2) ? OWVr : OWOr);
        float4 v = ((const float4*)src)[i];
        ((float4*)dst)[i] = make_float4(to_tf32(v.x), to_tf32(v.y), to_tf32(v.z), to_tf32(v.w));
        return;
    }
    bx -= 4096;
    if (bx < 2560){
        int idx = bx * 256 + threadIdx.x;
        int n = idx >> 11;
        int k = idx & 2047;
        int kk = k & 1023;
        float val = 0.f;
        if (n < 64){
            float w = w1[kk*64 + n];
            val = (k < 1024) ? w : x_w[kk]*w;
        } else if (n < 128){
            float w = a1[kk*64 + (n-64)];
            val = (k < 1024) ? w : x_a[kk]*w;
        } else if (n < 160){
            float w = v1[kk*32 + (n-128)];
            val = (k < 1024) ? w : x_v[kk]*w;
        } else if (n >= 192){
            float w = g1[kk*128 + (n-192)];
            val = (k < 1024) ? w : x_g[kk]*w;
        }
        Sg[OBU + idx] = to_tf32(val);
        return;
    }
    bx -= 2560;
    if (bx < 1152){
        int j = bx * 256 + threadIdx.x;
        if (j >= 294912) return;
        if      (j < 65536 )  do_tr(w2, Sg+OW2T, 64, 1024,  j);
        else if (j < 131072)  do_tr(a2, Sg+OA2T, 64, 1024,  j-65536);
        else if (j < 163840)  do_tr(v2, Sg+OV2T, 32, 1024,  j-131072);
        else                  do_tr(g2, Sg+OG2T, 128, 1024, j-163840);
        return;
    }
    bx -= 1152;
    {
        int row = bx;
        int t = row & (TT-1);
        int c4 = threadIdx.x;
        const float4* xv4 = (const float4*)x;
        float4 xc = xv4[(size_t)row*256 + c4];
        float4 xp = make_float4(0.f,0.f,0.f,0.f);
        if (t > 0) xp = xv4[(size_t)(row-1)*256 + c4];
        float4 dx = make_float4(xp.x-xc.x, xp.y-xc.y, xp.z-xc.z, xp.w-xc.w);
        size_t o = (size_t)row*256 + c4;
        float4 m;
        #define MIXOUT(dst, mp) \
            m = ((const float4*)mp)[c4]; \
            ((float4*)(Sg+dst))[o] = make_float4(to_tf32(xc.x+dx.x*m.x), to_tf32(xc.y+dx.y*m.y), \
                                                 to_tf32(xc.z+dx.z*m.z), to_tf32(xc.w+dx.w*m.w));
        MIXOUT(OXR, mr) MIXOUT(OXK, mk) MIXOUT(OXV, mv)
        #undef MIXOUT
        float4* xcp = (float4*)(Sg + OXC + (size_t)row*2048);
        xcp[c4]       = make_float4(to_tf32(xc.x), to_tf32(xc.y), to_tf32(xc.z), to_tf32(xc.w));
        xcp[256 + c4] = make_float4(to_tf32(dx.x), to_tf32(dx.y), to_tf32(dx.z), to_tf32(dx.w));
    }
}

// ---------------- H = act(Hlo + Hhi) ----------------
__global__ __launch_bounds__(256) void hsum_act(
    const float* __restrict__ Hlo, const float* __restrict__ Hhi, float* __restrict__ H)
{
    int i = blockIdx.x*256 + threadIdx.x;
    if (i >= 4096*80) return;
    int row = i / 80, q = i - row*80;
    int col = q*4;
    size_t off = (size_t)row*320 + col;
    float4 a = *(const float4*)&Hlo[off];
    float4 b = *(const float4*)&Hhi[off];
    float v[4] = {a.x+b.x, a.y+b.y, a.z+b.z, a.w+b.w};
    #pragma unroll
    for (int j=0;j<4;j++){
        int c = col + j;
        float xx = v[j];
        xx = (c < 64) ? tanhf(xx) : (c < 192 ? xx : sigm_(xx));
        v[j] = to_tf32(xx);
    }
    *(float4*)&H[off] = make_float4(v[0], v[1], v[2], v[3]);
}

// ---------------- scan-operand prep (with fused look-ahead MA/BG) ----------------
__global__ __launch_bounds__(256) void prep_kernel(
    const float* __restrict__ K, const float* __restrict__ A, const float* __restrict__ V,
    const float* __restrict__ WL, const float* __restrict__ VMIX, const float* __restrict__ vfirst,
    const float* __restrict__ k_k, const float* __restrict__ k_a,
    float* __restrict__ EW, float* __restrict__ BBo,
    float* __restrict__ K2o, float* __restrict__ Vo,
    float* __restrict__ MA, float* __restrict__ BG)
{
    int gw = (blockIdx.x*256 + threadIdx.x) >> 5;
    int lane = threadIdx.x & 31;
    int h = gw & 15, t = (gw >> 4) & 1023, b = gw >> 14;
    int c = h*64 + lane*2;
    size_t btc = ((size_t)(b*TT + t))*CC + c;
    float2 k  = *(const float2*)&K[btc];
    float2 kw = *(const float2*)&k_k[c];
    float2 ka = *(const float2*)&k_a[c];
    float2 a  = *(const float2*)&A[btc];
    float kk0 = k.x*kw.x, kk1 = k.y*kw.y;
    float2 kn = make_float2(0.f, 0.f);
    if (t < TT-1) kn = *(const float2*)&K[btc + CC];
    float kn0 = kn.x*kw.x, kn1 = kn.y*kw.y;
    float ss  = kk0*kk0 + kk1*kk1;
    float ssn = kn0*kn0 + kn1*kn1;
    #pragma unroll
    for (int off=16; off>0; off>>=1){
        ss  += __shfl_xor_sync(0xffffffffu, ss, off);
        ssn += __shfl_xor_sync(0xffffffffu, ssn, off);
    }
    float inv  = 1.f / fmaxf(sqrtf(ss), 1e-12f);
    float invn = 1.f / fmaxf(sqrtf(ssn), 1e-12f);
    kk0 *= inv; kk1 *= inv;
    float aan0 = -kn0*invn, aan1 = -kn1*invn;

    float2 wl = *(const float2*)&WL[btc];
    float2 v  = *(const float2*)&V[btc];
    float2 vf = *(const float2*)&vfirst[btc];
    float2 vm = *(const float2*)&VMIX[btc];
    v.x = v.x + (vf.x - v.x)*vm.x;
    v.y = v.y + (vf.y - v.y)*vm.y;
    float k20 = k.x*(1.f + (a.x-1.f)*ka.x);
    float k21 = k.y*(1.f + (a.y-1.f)*ka.y);
    float ew0 = expf(wl.x), ew1 = expf(wl.y);
    float bb0 = kk0*a.x, bb1 = kk1*a.y;

    float bsum = bb0*aan0 + bb1*aan1;
    float gsum = k20*aan0 + k21*aan1;
    #pragma unroll
    for (int off=16; off>0; off>>=1){
        bsum += __shfl_xor_sync(0xffffffffu, bsum, off);
        gsum += __shfl_xor_sync(0xffffffffu, gsum, off);
    }

    size_t bhtd = ((size_t)((b*HH + h)*TT + t))*64 + lane*2;
    *(float2*)&EW[bhtd]  = make_float2(ew0, ew1);
    *(float2*)&BBo[bhtd] = make_float2(bb0, bb1);
    *(float2*)&K2o[bhtd] = make_float2(k20, k21);
    *(float2*)&Vo[bhtd]  = v;
    *(float2*)&MA[bhtd]  = make_float2(ew0*aan0, ew1*aan1);
    if (lane == 0)
        *(float2*)&BG[((size_t)(b*HH + h)*TT + t)*2] = make_float2(bsum, gsum);
}

// ---------------- scan v4: look-ahead recurrence, 128 thr, 4 rows x 4 cols ----------------
__global__ void __launch_bounds__(128) scan_kernel(
    const float* __restrict__ EW, const float* __restrict__ BBp, const float* __restrict__ MAp,
    const float* __restrict__ K2p, const float* __restrict__ RB, const float* __restrict__ Vp,
    const float* __restrict__ BG, float* __restrict__ O4)
{
    __shared__ float sm[16*6*64];
    __shared__ float bg_sm[32];
    int bh = blockIdx.x >> 1;
    int b = bh >> 4, h = bh & 15;
    int rowBase = (blockIdx.x & 1) * 32;
    int tid = threadIdx.x;
    int cg = tid & 15;
    int rg = tid >> 4;
    int col0 = cg * 4;
    size_t base = (size_t)bh * TT * 64;
    size_t base4 = (size_t)bh * TT * 256;
    const float* BGp = BG + (size_t)bh * TT * 2;

    const float* mysrc = nullptr; int mystride = 64;
    int arr = tid >> 4, seg = tid & 15;
    if (tid < 96){
        switch (arr){
            case 0: mysrc = EW  + base; break;
            case 1: mysrc = BBp + base; break;
            case 2: mysrc = MAp + base; break;
            case 3: mysrc = K2p + base; break;
            case 4: mysrc = RB + (size_t)b*TT*CC + h*64; mystride = CC; break;
            case 5: mysrc = Vp  + base; break;
        }
    }
    uint32_t smb = (uint32_t)__cvta_generic_to_shared(sm);
    uint32_t smbg = (uint32_t)__cvta_generic_to_shared(bg_sm);

    auto pf4 = [&](int batch){
        if (tid < 96){
            #pragma unroll
            for (int u=0; u<4; u++){
                int t = batch*4 + u;
                const float* g = mysrc + (size_t)t*mystride + seg*4;
                unsigned sa = smb + 4u*(uint32_t)(((t&15)*384) + arr*64 + seg*4);
                asm volatile("cp.async.ca.shared.global [%0], [%1], 16;"::"r"(sa),"l"(g));
            }
        } else if (tid < 98){
            const float* g = BGp + (size_t)batch*8 + (tid-96)*4;
            unsigned sa = smbg + 4u*(uint32_t)((((batch*4)&15)*2) + (tid-96)*4);
            asm volatile("cp.async.ca.shared.global [%0], [%1], 16;"::"r"(sa),"l"(g));
        }
        asm volatile("cp.async.commit_group;");
    };

    pf4(0); pf4(1); pf4(2);

    u64 S2[4][2];
    float sab[4];
    #pragma unroll
    for (int j=0;j<4;j++){ S2[j][0]=0ull; S2[j][1]=0ull; sab[j]=0.f; }

    for (int i=0; i<256; i++){
        asm volatile("cp.async.wait_group 2;");
        __syncthreads();
        if (i+3 < 256) pf4(i+3);
        else asm volatile("cp.async.commit_group;");
        int tb = i*4;

        #pragma unroll
        for (int u=0; u<4; u++){
            const float* st = &sm[((tb+u) & 15) * 384];
            u64 ew2[2], bb2[2], ma2[2], kk2[2], rr2[2];
            #define LD2(dst, off) { \
                ulonglong2 q = *(const ulonglong2*)&st[(off)+col0]; \
                dst[0]=q.x; dst[1]=q.y; }
            LD2(ew2,   0) LD2(bb2,  64) LD2(ma2, 128) LD2(kk2, 192) LD2(rr2, 256)
            #undef LD2
            float vv[4];
            #pragma unroll
            for (int j=0;j<4;j++) vv[j] = st[320 + rowBase + rg + 8*j];
            float2 bg = *(const float2*)&bg_sm[((tb+u)&15)*2];

            float Dp[4];
            #pragma unroll
            for (int j=0;j<4;j++)
                Dp[j] = HADD2(FMA2(S2[j][1], ma2[1], MUL2(S2[j][0], ma2[0])));
            #pragma unroll
            for (int j=0;j<4;j++){
                Dp[j] += __shfl_xor_sync(0xffffffffu, Dp[j], 1);
                Dp[j] += __shfl_xor_sync(0xffffffffu, Dp[j], 2);
                Dp[j] += __shfl_xor_sync(0xffffffffu, Dp[j], 4);
                Dp[j] += __shfl_xor_sync(0xffffffffu, Dp[j], 8);
            }

            float po[4];
            #pragma unroll
            for (int j=0;j<4;j++){
                u64 sab2 = PK2(sab[j]), vv2 = PK2(vv[j]);
                S2[j][0] = FMA2(kk2[0], vv2, FMA2(bb2[0], sab2, MUL2(S2[j][0], ew2[0])));
                S2[j][1] = FMA2(kk2[1], vv2, FMA2(bb2[1], sab2, MUL2(S2[j][1], ew2[1])));
                po[j] = HADD2(FMA2(S2[j][1], rr2[1], MUL2(S2[j][0], rr2[0])));
                po[j] += __shfl_xor_sync(0xffffffffu, po[j], 1);
                po[j] += __shfl_xor_sync(0xffffffffu, po[j], 2);
            }
            #pragma unroll
            for (int j=0;j<4;j++)
                sab[j] = Dp[j] + sab[j]*bg.x + vv[j]*bg.y;

            if ((tid & 3) == 0){
                size_t ob = base4 + (size_t)(tb+u)*256;
                int p = cg >> 2;
                #pragma unroll
                for (int j=0;j<4;j++)
                    O4[ob + (size_t)(rowBase + rg + 8*j)*4 + p] = po[j];
            }
        }
    }
}

// ---------------- post: sum partials + groupnorm + bonus + gate ----------------
__global__ __launch_bounds__(256) void post_kernel(
    const float* __restrict__ O4, const float* __restrict__ RB, const float* __restrict__ K2p,
    const float* __restrict__ Vp, const float* __restrict__ G,
    const float* __restrict__ r_k, const float* __restrict__ gn_w, const float* __restrict__ gn_b,
    float* __restrict__ Z)
{
    int gw = (blockIdx.x*256 + threadIdx.x) >> 5;
    int lane = threadIdx.x & 31;
    int h = gw & 15, t = (gw >> 4) & 1023, b = gw >> 14;
    size_t bhtd = ((size_t)((b*HH + h)*TT + t))*64 + lane*2;
    int c = h*64 + lane*2;
    size_t btc = ((size_t)(b*TT + t))*CC + c;

    size_t b4 = ((size_t)(b*HH + h))*TT*256 + (size_t)t*256 + (size_t)lane*8;
    float4 pa = *(const float4*)&O4[b4];
    float4 pb = *(const float4*)&O4[b4 + 4];
    float2 o = make_float2(pa.x+pa.y+pa.z+pa.w, pb.x+pb.y+pb.z+pb.w);

    float sm = o.x + o.y;
    #pragma unroll
    for (int off=16; off>0; off>>=1) sm += __shfl_xor_sync(0xffffffffu, sm, off);
    float mean = sm * (1.f/64.f);
    float dx = o.x - mean, dy = o.y - mean;
    float vs = dx*dx + dy*dy;
    #pragma unroll
    for (int off=16; off>0; off>>=1) vs += __shfl_xor_sync(0xffffffffu, vs, off);
    float inv = rsqrtf(vs*(1.f/64.f) + GN_EPS);

    float2 r  = *(const float2*)&RB[btc];
    float2 k2 = *(const float2*)&K2p[bhtd];
    float2 v  = *(const float2*)&Vp[bhtd];
    float2 rk = *(const float2*)&r_k[c];
    float bs = r.x*k2.x*rk.x + r.y*k2.y*rk.y;
    #pragma unroll
    for (int off=16; off>0; off>>=1) bs += __shfl_xor_sync(0xffffffffu, bs, off);

    float2 g  = *(const float2*)&G[btc];
    float2 w  = *(const float2*)&gn_w[c];
    float2 bb = *(const float2*)&gn_b[c];
    float z0 = ((dx*inv)*w.x + bb.x + bs*v.x) * g.x;
    float z1 = ((dy*inv)*w.y + bb.y + bs*v.y) * g.y;
    *(float2*)&Z[btc] = make_float2(to_tf32(z0), to_tf32(z1));
}

// ---------------- driver ----------------
static inline GJob mkjob(const float* A, int lda, const float* B, int ldb, float* C, int ldc,
                         int N, int K, const float* bias, int mode, float scale, int ro,
                         int nrep, int ny){
    GJob j; j.A=A; j.B=B; j.C=C; j.bias=bias; j.lda=lda; j.ldb=ldb; j.ldc=ldc;
    j.N=N; j.K=K; j.mode=mode; j.scale=scale; j.round_out=ro; j.nrep=nrep; j.ny=ny; return j;
}

extern "C" void kernel_launch(void* const* d_in, const int* in_sizes, int n_in,
                              void* d_out, int out_size) {
    const float* x   = (const float*)d_in[0];
    const float* vfi = (const float*)d_in[1];
    const float* x_r = (const float*)d_in[2];
    const float* x_w = (const float*)d_in[3];
    const float* x_k = (const float*)d_in[4];
    const float* x_v = (const float*)d_in[5];
    const float* x_a = (const float*)d_in[6];
    const float* x_g = (const float*)d_in[7];
    const float* Wr  = (const float*)d_in[8];
    const float* Wk  = (const float*)d_in[9];
    const float* Wv  = (const float*)d_in[10];
    const float* Wo  = (const float*)d_in[11];
    const float* w0  = (const float*)d_in[12];
    const float* w1  = (const float*)d_in[13];
    const float* w2  = (const float*)d_in[14];
    const float* a0  = (const float*)d_in[15];
    const float* a1  = (const float*)d_in[16];
    const float* a2  = (const float*)d_in[17];
    const float* v0  = (const float*)d_in[18];
    const float* v1  = (const float*)d_in[19];
    const float* v2  = (const float*)d_in[20];
    const float* g1  = (const float*)d_in[21];
    const float* g2  = (const float*)d_in[22];
    const float* k_k = (const float*)d_in[23];
    const float* k_a = (const float*)d_in[24];
    const float* r_k = (const float*)d_in[25];
    const float* gnw = (const float*)d_in[26];
    const float* gnb = (const float*)d_in[27];
    float* out = (float*)d_out;

    float* S;
    cudaGetSymbolAddress((void**)&S, gScratch);

    const int SM128 = 3*(128+128)*32*4;   // 98304
    const int SM64  = 3*(128+64)*32*4;    // 73728
    cudaFuncSetAttribute(gemm_mma<128>, cudaFuncAttributeMaxDynamicSharedMemorySize, SM128);
    cudaFuncSetAttribute(gemm_mma<64>,  cudaFuncAttributeMaxDynamicSharedMemorySize, SM64);

    const int M = BB*TT;
    float* H = S + OHST;

    // 0: fused elementwise prep
    elem_prep<<<4096+2560+1152+4096, 256>>>(Wr, Wk, Wv, Wo, w1, a1, v1, g1, w2, a2, v2, g2,
                                            x_w, x_a, x_v, x_g, x, x_r, x_k, x_v, S);
    // 1: stage-1 split-K halves
    {
        GPack p{};
        p.j[0] = mkjob(S+OXC,      2048, S+OBU,      2048, S+OHLO, 320, 320, 1024, nullptr, 0, 1.f, 0, 1, 5);
        p.j[1] = mkjob(S+OXC+1024, 2048, S+OBU+1024, 2048, S+OHHI, 320, 320, 1024, nullptr, 0, 1.f, 0, 1, 5);
        gemm_mma<64><<<dim3(M/128,5,2), 256, SM64>>>(p);
    }
    // 2: H = act(Hlo + Hhi)
    hsum_act<<<1280, 256>>>(S+OHLO, S+OHHI, H);
    // 3: MERGED: stage-2 (latency-bound, z=0..3 first) + R/K/V (z=4..6)  <-- profiled (idx 3)
    {
        GPack p{};
        p.j[0] = mkjob(H+0,   320, S+OW2T, 64,  S+OWL,  1024, 1024, 64,  w0, 2, LOG_DECAY, 0, 4, 2);
        p.j[1] = mkjob(H+64,  320, S+OA2T, 64,  S+OAB,  1024, 1024, 64,  a0, 2, 1.f, 0, 4, 2);
        p.j[2] = mkjob(H+128, 320, S+OV2T, 32,  S+OVMX, 1024, 1024, 32,  v0, 2, 1.f, 0, 4, 2);
        p.j[3] = mkjob(H+192, 320, S+OG2T, 128, S+OGB,  1024, 1024, 128, nullptr, 0, 1.f, 0, 4, 2);
        p.j[4] = mkjob(S+OXR, 1024, S+OWRr, 1024, S+ORB, 1024, 1024, 1024, nullptr, 0, 1.f, 0, 1, 8);
        p.j[5] = mkjob(S+OXK, 1024, S+OWKr, 1024, S+OKB, 1024, 1024, 1024, nullptr, 0, 1.f, 0, 1, 8);
        p.j[6] = mkjob(S+OXV, 1024, S+OWVr, 1024, S+OVB, 1024, 1024, 1024, nullptr, 0, 1.f, 0, 1, 8);
        gemm_mma<128><<<dim3(M/128,8,7), 256, SM128>>>(p);
    }
    // 4: scan operand prep (fused look-ahead MA/BG)
    prep_kernel<<<(BB*TT*HH*32)/256, 256>>>(S+OKB, S+OAB, S+OVB, S+OWL, S+OVMX, vfi,
                                            k_k, k_a,
                                            S+OEW, S+OBBA, S+OKK2, S+OVVA, S+OMA, S+OBG);
    // 5: sequential scan v4 (128 CTAs, 32 rows each)
    scan_kernel<<<BB*HH*2, 128>>>(S+OEW, S+OBBA, S+OMA, S+OKK2, S+ORB, S+OVVA, S+OBG, S+OO4);
    // 6: sum partials + groupnorm + bonus + gate
    post_kernel<<<(BB*TT*HH*32)/256, 256>>>(S+OO4, S+ORB, S+OKK2, S+OVVA, S+OGB,
                                            r_k, gnw, gnb, S+OZB);
    // 7: out = Z @ Wo^T
    {
        GPack p{};
        p.j[0] = mkjob(S+OZB, 1024, S+OWOr, 1024, out, 1024, 1024, 1024, nullptr, 0, 1.f, 0, 1, 8);
        gemm_mma<128><<<dim3(M/128,8,1), 256, SM128>>>(p);
    }
    // v_first passthrough
    if (out_size >= 2*NE){
        cudaMemcpyAsync(out + NE, vfi, (size_t)NE*sizeof(float), cudaMemcpyDeviceToDevice);
    }
}

// round 17
// speedup vs baseline: 1.1633x; 1.1187x over previous
#include <cuda_runtime.h>
#include <math.h>
#include <stdint.h>

#define BB 4
#define TT 1024
#define CC 1024
#define HH 16
#define DD 64
#define NE 4194304     // B*T*C
#define LOG_DECAY (-0.6065306597126334f)
#define GN_EPS 64e-5f

typedef unsigned long long u64;

// ---------------- static scratch ----------------
__device__ float gScratch[104857600];

#define OO4  ((size_t)0)               // scan partials (slots 0-3)
#define OXR  ((size_t)0*NE)
#define OXK  ((size_t)2*NE)
#define OXV  ((size_t)3*NE)
#define OXC  ((size_t)4*NE)            // [x | xx] (slots 4-5)
#define ORB  ((size_t)6*NE)
#define OKB  ((size_t)7*NE)
#define OVB  ((size_t)8*NE)
#define OAB  ((size_t)9*NE)
#define OGB  ((size_t)10*NE)
#define OWL  ((size_t)11*NE)
#define OVMX ((size_t)12*NE)
#define OHST ((size_t)13*NE)
#define OHLO ((size_t)14*NE)           // dead after hsum_act -> reused as MA
#define OHHI ((size_t)15*NE)           // dead after hsum_act -> reused as BG
#define OMA  OHLO
#define OBG  OHHI
#define OEW  ((size_t)16*NE)
#define OBBA ((size_t)17*NE)
#define OKK2 ((size_t)19*NE)
#define OVVA ((size_t)20*NE)
#define OZB  ((size_t)21*NE)
#define OW2T ((size_t)22*NE)
#define OA2T (OW2T + 65536)
#define OV2T (OA2T + 65536)
#define OG2T (OV2T + 32768)
#define OWRr (OG2T + 131072)
#define OWKr (OWRr + 1048576)
#define OWVr (OWKr + 1048576)
#define OWOr (OWVr + 1048576)
#define OBU  (OWOr + 1048576)

__device__ __forceinline__ float to_tf32(float x){
    uint32_t u; asm("cvt.rna.tf32.f32 %0, %1;" : "=r"(u) : "f"(x));
    return __uint_as_float(u);
}
__device__ __forceinline__ float sigm_(float x){ return 1.f/(1.f+expf(-x)); }

__device__ __forceinline__ void mma8(float* d, const uint32_t* a, const uint32_t* b){
    asm volatile("mma.sync.aligned.m16n8k8.row.col.f32.tf32.tf32.f32 "
        "{%0,%1,%2,%3}, {%4,%5,%6,%7}, {%8,%9}, {%0,%1,%2,%3};"
        : "+f"(d[0]), "+f"(d[1]), "+f"(d[2]), "+f"(d[3])
        : "r"(a[0]), "r"(a[1]), "r"(a[2]), "r"(a[3]), "r"(b[0]), "r"(b[1]));
}
__device__ __forceinline__ void ldsm4(uint32_t* r, uint32_t a){
    asm volatile("ldmatrix.sync.aligned.m8n8.x4.shared.b16 {%0,%1,%2,%3}, [%4];"
        : "=r"(r[0]),"=r"(r[1]),"=r"(r[2]),"=r"(r[3]) : "r"(a));
}
__device__ __forceinline__ int swz(int r, int c){
    return r*32 + (int)((((((unsigned)c>>2) ^ ((unsigned)r & 7u)) << 2)) | ((unsigned)c & 3u));
}

// f32x2 packed math helpers
__device__ __forceinline__ u64 FMA2(u64 a, u64 b, u64 c){
    u64 d; asm("fma.rn.f32x2 %0, %1, %2, %3;" : "=l"(d) : "l"(a), "l"(b), "l"(c)); return d;
}
__device__ __forceinline__ u64 MUL2(u64 a, u64 b){
    u64 d; asm("mul.rn.f32x2 %0, %1, %2;" : "=l"(d) : "l"(a), "l"(b)); return d;
}
__device__ __forceinline__ u64 PK2(float x){
    u64 d; asm("mov.b64 %0, {%1, %1};" : "=l"(d) : "f"(x)); return d;
}
__device__ __forceinline__ float HADD2(u64 d){
    float a, b; asm("mov.b64 {%0, %1}, %2;" : "=f"(a), "=f"(b) : "l"(d)); return a + b;
}

// ---------------- job descriptor for batched GEMM ----------------
struct GJob {
    const float* A; const float* B; float* C; const float* bias;
    int lda, ldb, ldc, N, K, mode; float scale; int round_out; int nrep; int ny;
};
struct GPack { GJob j[8]; };

// ---------------- tf32 GEMM: C = A * B^T, z-batched pack, pipelined n-rep, ny early-exit ----
template<int NT>
__global__ void __launch_bounds__(256,2) gemm_mma(GPack p)
{
    extern __shared__ float sm[];
    const int AS  = 128*32;
    const int STG = (128+NT)*32;
    const int NTN = (NT==128) ? 8 : 4;
    const int NLD = NTN/2;

    GJob jb = p.j[blockIdx.z];
    if ((int)blockIdx.y >= jb.ny) return;

    int tid = threadIdx.x, wid = tid >> 5, lane = tid & 31;
    int bm0 = blockIdx.x * 128;
    int grp = lane >> 2, thr = lane & 3;
    int wm = (wid & 3) * 32;
    int wn = (NT==128) ? (wid >> 2) * 64 : (wid >> 2) * 32;
    int NC = jb.K >> 5;
    int total = jb.nrep * NC;
    int bnBase = blockIdx.y * jb.nrep;

    uint32_t smb = (uint32_t)__cvta_generic_to_shared(sm);

    uint32_t aoff[2][4], boff[NLD][4];
    #pragma unroll
    for (int mt=0;mt<2;mt++)
      #pragma unroll
      for (int kk=0;kk<4;kk++){
        int row = wm + mt*16 + (lane & 15);
        int col = kk*8 + (lane >> 4) * 4;
        aoff[mt][kk] = 4u * (uint32_t)swz(row, col);
      }
    #pragma unroll
    for (int np=0;np<NLD;np++)
      #pragma unroll
      for (int kk=0;kk<4;kk++){
        int row = wn + np*16 + (lane & 7) + ((lane >> 4) & 1) * 8;
        int col = kk*8 + ((lane >> 3) & 1) * 4;
        boff[np][kk] = 4u * (uint32_t)(AS + swz(row, col));
      }

    int ar = tid >> 3, aj = tid & 7;

    auto load_stage = [&](int stg, int rep, int c){
        const float* Ag = jb.A + (size_t)bm0 * jb.lda + c*32;
        #pragma unroll
        for (int i=0;i<4;i++){
            int r = ar + 32*i;
            unsigned dst = smb + 4u*(uint32_t)(stg*STG + swz(r, aj*4));
            const float* src = Ag + (size_t)r*jb.lda + aj*4;
            asm volatile("cp.async.cg.shared.global [%0], [%1], 16;"::"r"(dst),"l"(src));
        }
        int bn = (bnBase + rep) * NT;
        const float* Bg = jb.B + (size_t)bn * jb.ldb + c*32;
        #pragma unroll
        for (int i=0;i<NT/32;i++){
            int r = ar + 32*i;
            unsigned dst = smb + 4u*(uint32_t)(stg*STG + AS + swz(r, aj*4));
            const float* src = Bg + (size_t)r*jb.ldb + aj*4;
            asm volatile("cp.async.cg.shared.global [%0], [%1], 16;"::"r"(dst),"l"(src));
        }
    };

    float acc[2][NTN][4];
    #pragma unroll
    for (int i=0;i<2;i++)
      #pragma unroll
      for (int j=0;j<NTN;j++)
        #pragma unroll
        for (int l=0;l<4;l++) acc[i][j][l]=0.f;

    int pr = 0, pc = 0;
    load_stage(0, pr, pc);
    if (++pc == NC){ pc = 0; ++pr; }
    asm volatile("cp.async.commit_group;");
    if (total > 1){
        load_stage(1, pr, pc);
        if (++pc == NC){ pc = 0; ++pr; }
    }
    asm volatile("cp.async.commit_group;");

    int cstg = 0, pstg = 2;
    int cc = 0, erep = 0;
    uint32_t sb = smb;
    for (int tc = 0; tc < total; tc++){
        asm volatile("cp.async.wait_group 1;");
        __syncthreads();
        #pragma unroll
        for (int kk=0; kk<4; kk++){
            uint32_t af[2][4];
            ldsm4(af[0], sb + aoff[0][kk]);
            ldsm4(af[1], sb + aoff[1][kk]);
            uint32_t bf[NLD][4];
            #pragma unroll
            for (int np=0;np<NLD;np++) ldsm4(bf[np], sb + boff[np][kk]);
            #pragma unroll
            for (int mt=0;mt<2;mt++)
                #pragma unroll
                for (int nt=0;nt<NTN;nt++)
                    mma8(acc[mt][nt], af[mt], &bf[nt>>1][(nt&1)*2]);
        }
        if (tc + 2 < total){
            load_stage(pstg, pr, pc);
            if (++pc == NC){ pc = 0; ++pr; }
        }
        asm volatile("cp.async.commit_group;");
        if (++cstg == 3){ cstg = 0; sb = smb; } else sb += 4u*STG;
        if (++pstg == 3) pstg = 0;

        if (++cc == NC){
            cc = 0;
            int bn0 = (bnBase + erep) * NT;
            ++erep;
            #pragma unroll
            for (int mt=0;mt<2;mt++){
                #pragma unroll
                for (int nt=0;nt<NTN;nt++){
                    #pragma unroll
                    for (int half=0; half<2; half++){
                        int row = bm0 + wm + mt*16 + grp + half*8;
                        int col = bn0 + wn + nt*8 + thr*2;
                        float v0 = acc[mt][nt][half*2+0];
                        float v1 = acc[mt][nt][half*2+1];
                        if (jb.bias){ v0 += jb.bias[col]; v1 += jb.bias[col+1]; }
                        if (jb.mode==1){ v0 = tanhf(v0); v1 = tanhf(v1); }
                        else if (jb.mode==2){ v0 = jb.scale*sigm_(v0); v1 = jb.scale*sigm_(v1); }
                        else if (jb.mode==3){
                            v0 = (col   < 64) ? tanhf(v0) : (col   < 192 ? v0 : sigm_(v0));
                            v1 = (col+1 < 64) ? tanhf(v1) : (col+1 < 192 ? v1 : sigm_(v1));
                        }
                        if (jb.round_out){ v0 = to_tf32(v0); v1 = to_tf32(v1); }
                        float* cp = jb.C + (size_t)row*jb.ldc + col;
                        cp[0] = v0; cp[1] = v1;
                        acc[mt][nt][half*2+0] = 0.f;
                        acc[mt][nt][half*2+1] = 0.f;
                    }
                }
            }
        }
    }
}

// ---------------- fused elementwise prep: weights(vec4) + BU + transposes + mix ----------------
__device__ __forceinline__ void do_tr(const float* src, float* dst, int rows, int cols, int li){
    int r = li / cols, c = li - r * cols;
    dst[(size_t)c * rows + r] = to_tf32(src[li]);
}
__global__ __launch_bounds__(256) void elem_prep(
    const float* __restrict__ Wr, const float* __restrict__ Wk,
    const float* __restrict__ Wv, const float* __restrict__ Wo,
    const float* __restrict__ w1, const float* __restrict__ a1,
    const float* __restrict__ v1, const float* __restrict__ g1,
    const float* __restrict__ w2, const float* __restrict__ a2,
    const float* __restrict__ v2, const float* __restrict__ g2,
    const float* __restrict__ x_w, const float* __restrict__ x_a,
    const float* __restrict__ x_v, const float* __restrict__ x_g,
    const float* __restrict__ x,
    const float* __restrict__ mr, const float* __restrict__ mk, const float* __restrict__ mv,
    float* __restrict__ Sg)
{
    int bx = blockIdx.x;
    if (bx < 4096){
        int idx = bx * 256 + threadIdx.x;
        int m = idx >> 18;
        int i = idx & 262143;
        const float* src = (m == 0) ? Wr : (m == 1) ? Wk : (m == 2) ? Wv : Wo;
        float* dst = Sg + ((m == 0) ? OWRr : (m == 1) ? OWKr : (m == 2) ? OWVr : OWOr);
        float4 v = ((const float4*)src)[i];
        ((float4*)dst)[i] = make_float4(to_tf32(v.x), to_tf32(v.y), to_tf32(v.z), to_tf32(v.w));
        return;
    }
    bx -= 4096;
    if (bx < 2560){
        int idx = bx * 256 + threadIdx.x;
        int n = idx >> 11;
        int k = idx & 2047;
        int kk = k & 1023;
        float val = 0.f;
        if (n < 64){
            float w = w1[kk*64 + n];
            val = (k < 1024) ? w : x_w[kk]*w;
        } else if (n < 128){
            float w = a1[kk*64 + (n-64)];
            val = (k < 1024) ? w : x_a[kk]*w;
        } else if (n < 160){
            float w = v1[kk*32 + (n-128)];
            val = (k < 1024) ? w : x_v[kk]*w;
        } else if (n >= 192){
            float w = g1[kk*128 + (n-192)];
            val = (k < 1024) ? w : x_g[kk]*w;
        }
        Sg[OBU + idx] = to_tf32(val);
        return;
    }
    bx -= 2560;
    if (bx < 1152){
        int j = bx * 256 + threadIdx.x;
        if (j >= 294912) return;
        if      (j < 65536 )  do_tr(w2, Sg+OW2T, 64, 1024,  j);
        else if (j < 131072)  do_tr(a2, Sg+OA2T, 64, 1024,  j-65536);
        else if (j < 163840)  do_tr(v2, Sg+OV2T, 32, 1024,  j-131072);
        else                  do_tr(g2, Sg+OG2T, 128, 1024, j-163840);
        return;
    }
    bx -= 1152;
    {
        int row = bx;
        int t = row & (TT-1);
        int c4 = threadIdx.x;
        const float4* xv4 = (const float4*)x;
        float4 xc = xv4[(size_t)row*256 + c4];
        float4 xp = make_float4(0.f,0.f,0.f,0.f);
        if (t > 0) xp = xv4[(size_t)(row-1)*256 + c4];
        float4 dx = make_float4(xp.x-xc.x, xp.y-xc.y, xp.z-xc.z, xp.w-xc.w);
        size_t o = (size_t)row*256 + c4;
        float4 m;
        #define MIXOUT(dst, mp) \
            m = ((const float4*)mp)[c4]; \
            ((float4*)(Sg+dst))[o] = make_float4(to_tf32(xc.x+dx.x*m.x), to_tf32(xc.y+dx.y*m.y), \
                                                 to_tf32(xc.z+dx.z*m.z), to_tf32(xc.w+dx.w*m.w));
        MIXOUT(OXR, mr) MIXOUT(OXK, mk) MIXOUT(OXV, mv)
        #undef MIXOUT
        float4* xcp = (float4*)(Sg + OXC + (size_t)row*2048);
        xcp[c4]       = make_float4(to_tf32(xc.x), to_tf32(xc.y), to_tf32(xc.z), to_tf32(xc.w));
        xcp[256 + c4] = make_float4(to_tf32(dx.x), to_tf32(dx.y), to_tf32(dx.z), to_tf32(dx.w));
    }
}

// ---------------- H = act(Hlo + Hhi) ----------------
__global__ __launch_bounds__(256) void hsum_act(
    const float* __restrict__ Hlo, const float* __restrict__ Hhi, float* __restrict__ H)
{
    int i = blockIdx.x*256 + threadIdx.x;
    if (i >= 4096*80) return;
    int row = i / 80, q = i - row*80;
    int col = q*4;
    size_t off = (size_t)row*320 + col;
    float4 a = *(const float4*)&Hlo[off];
    float4 b = *(const float4*)&Hhi[off];
    float v[4] = {a.x+b.x, a.y+b.y, a.z+b.z, a.w+b.w};
    #pragma unroll
    for (int j=0;j<4;j++){
        int c = col + j;
        float xx = v[j];
        xx = (c < 64) ? tanhf(xx) : (c < 192 ? xx : sigm_(xx));
        v[j] = to_tf32(xx);
    }
    *(float4*)&H[off] = make_float4(v[0], v[1], v[2], v[3]);
}

// ---------------- scan-operand prep (with fused look-ahead MA/BG) ----------------
__global__ __launch_bounds__(256) void prep_kernel(
    const float* __restrict__ K, const float* __restrict__ A, const float* __restrict__ V,
    const float* __restrict__ WL, const float* __restrict__ VMIX, const float* __restrict__ vfirst,
    const float* __restrict__ k_k, const float* __restrict__ k_a,
    float* __restrict__ EW, float* __restrict__ BBo,
    float* __restrict__ K2o, float* __restrict__ Vo,
    float* __restrict__ MA, float* __restrict__ BG)
{
    int gw = (blockIdx.x*256 + threadIdx.x) >> 5;
    int lane = threadIdx.x & 31;
    int h = gw & 15, t = (gw >> 4) & 1023, b = gw >> 14;
    int c = h*64 + lane*2;
    size_t btc = ((size_t)(b*TT + t))*CC + c;
    float2 k  = *(const float2*)&K[btc];
    float2 kw = *(const float2*)&k_k[c];
    float2 ka = *(const float2*)&k_a[c];
    float2 a  = *(const float2*)&A[btc];
    float kk0 = k.x*kw.x, kk1 = k.y*kw.y;
    float2 kn = make_float2(0.f, 0.f);
    if (t < TT-1) kn = *(const float2*)&K[btc + CC];
    float kn0 = kn.x*kw.x, kn1 = kn.y*kw.y;
    float ss  = kk0*kk0 + kk1*kk1;
    float ssn = kn0*kn0 + kn1*kn1;
    #pragma unroll
    for (int off=16; off>0; off>>=1){
        ss  += __shfl_xor_sync(0xffffffffu, ss, off);
        ssn += __shfl_xor_sync(0xffffffffu, ssn, off);
    }
    float inv  = 1.f / fmaxf(sqrtf(ss), 1e-12f);
    float invn = 1.f / fmaxf(sqrtf(ssn), 1e-12f);
    kk0 *= inv; kk1 *= inv;
    float aan0 = -kn0*invn, aan1 = -kn1*invn;

    float2 wl = *(const float2*)&WL[btc];
    float2 v  = *(const float2*)&V[btc];
    float2 vf = *(const float2*)&vfirst[btc];
    float2 vm = *(const float2*)&VMIX[btc];
    v.x = v.x + (vf.x - v.x)*vm.x;
    v.y = v.y + (vf.y - v.y)*vm.y;
    float k20 = k.x*(1.f + (a.x-1.f)*ka.x);
    float k21 = k.y*(1.f + (a.y-1.f)*ka.y);
    float ew0 = expf(wl.x), ew1 = expf(wl.y);
    float bb0 = kk0*a.x, bb1 = kk1*a.y;

    float bsum = bb0*aan0 + bb1*aan1;
    float gsum = k20*aan0 + k21*aan1;
    #pragma unroll
    for (int off=16; off>0; off>>=1){
        bsum += __shfl_xor_sync(0xffffffffu, bsum, off);
        gsum += __shfl_xor_sync(0xffffffffu, gsum, off);
    }

    size_t bhtd = ((size_t)((b*HH + h)*TT + t))*64 + lane*2;
    *(float2*)&EW[bhtd]  = make_float2(ew0, ew1);
    *(float2*)&BBo[bhtd] = make_float2(bb0, bb1);
    *(float2*)&K2o[bhtd] = make_float2(k20, k21);
    *(float2*)&Vo[bhtd]  = v;
    *(float2*)&MA[bhtd]  = make_float2(ew0*aan0, ew1*aan1);
    if (lane == 0)
        *(float2*)&BG[((size_t)(b*HH + h)*TT + t)*2] = make_float2(bsum, gsum);
}

// ---------------- scan v4b: look-ahead recurrence, 128 thr, 32-stage ring, 8 steps/barrier ----
__global__ void __launch_bounds__(128) scan_kernel(
    const float* __restrict__ EW, const float* __restrict__ BBp, const float* __restrict__ MAp,
    const float* __restrict__ K2p, const float* __restrict__ RB, const float* __restrict__ Vp,
    const float* __restrict__ BG, float* __restrict__ O4)
{
    __shared__ float sm[32*6*64];    // 32 stages x 384 floats = 48KB
    __shared__ float bg_sm[64];      // 32 stages x {beta, gamma}
    int bh = blockIdx.x >> 1;
    int b = bh >> 4, h = bh & 15;
    int rowBase = (blockIdx.x & 1) * 32;
    int tid = threadIdx.x;
    int cg = tid & 15;
    int rg = tid >> 4;
    int col0 = cg * 4;
    size_t base = (size_t)bh * TT * 64;
    size_t base4 = (size_t)bh * TT * 256;
    const float* BGp = BG + (size_t)bh * TT * 2;

    const float* mysrc = nullptr; int mystride = 64;
    int arr = tid >> 4, seg = tid & 15;
    if (tid < 96){
        switch (arr){
            case 0: mysrc = EW  + base; break;
            case 1: mysrc = BBp + base; break;
            case 2: mysrc = MAp + base; break;
            case 3: mysrc = K2p + base; break;
            case 4: mysrc = RB + (size_t)b*TT*CC + h*64; mystride = CC; break;
            case 5: mysrc = Vp  + base; break;
        }
    }
    uint32_t smb = (uint32_t)__cvta_generic_to_shared(sm);
    uint32_t smbg = (uint32_t)__cvta_generic_to_shared(bg_sm);

    auto pf8 = [&](int batch){
        if (tid < 96){
            #pragma unroll
            for (int u=0; u<8; u++){
                int t = batch*8 + u;
                const float* g = mysrc + (size_t)t*mystride + seg*4;
                unsigned sa = smb + 4u*(uint32_t)(((t&31)*384) + arr*64 + seg*4);
                asm volatile("cp.async.ca.shared.global [%0], [%1], 16;"::"r"(sa),"l"(g));
            }
        } else if (tid < 100){
            const float* g = BGp + (size_t)batch*16 + (tid-96)*4;
            unsigned sa = smbg + 4u*(uint32_t)((((batch*8)&31)*2) + (tid-96)*4);
            asm volatile("cp.async.ca.shared.global [%0], [%1], 16;"::"r"(sa),"l"(g));
        }
        asm volatile("cp.async.commit_group;");
    };

    pf8(0); pf8(1); pf8(2);

    u64 S2[4][2];
    float sab[4];
    #pragma unroll
    for (int j=0;j<4;j++){ S2[j][0]=0ull; S2[j][1]=0ull; sab[j]=0.f; }

    for (int i=0; i<128; i++){
        asm volatile("cp.async.wait_group 2;");
        __syncthreads();
        if (i+3 < 128) pf8(i+3);
        else asm volatile("cp.async.commit_group;");
        int tb = i*8;

        #pragma unroll
        for (int u=0; u<8; u++){
            const float* st = &sm[((tb+u) & 31) * 384];
            u64 ew2[2], bb2[2], ma2[2], kk2[2], rr2[2];
            #define LD2(dst, off) { \
                ulonglong2 q = *(const ulonglong2*)&st[(off)+col0]; \
                dst[0]=q.x; dst[1]=q.y; }
            LD2(ew2,   0) LD2(bb2,  64) LD2(ma2, 128) LD2(kk2, 192) LD2(rr2, 256)
            #undef LD2
            float vv[4];
            #pragma unroll
            for (int j=0;j<4;j++) vv[j] = st[320 + rowBase + rg + 8*j];
            float2 bg = *(const float2*)&bg_sm[((tb+u)&31)*2];

            float Dp[4];
            #pragma unroll
            for (int j=0;j<4;j++)
                Dp[j] = HADD2(FMA2(S2[j][1], ma2[1], MUL2(S2[j][0], ma2[0])));
            #pragma unroll
            for (int j=0;j<4;j++){
                Dp[j] += __shfl_xor_sync(0xffffffffu, Dp[j], 1);
                Dp[j] += __shfl_xor_sync(0xffffffffu, Dp[j], 2);
                Dp[j] += __shfl_xor_sync(0xffffffffu, Dp[j], 4);
                Dp[j] += __shfl_xor_sync(0xffffffffu, Dp[j], 8);
            }

            float po[4];
            #pragma unroll
            for (int j=0;j<4;j++){
                u64 sab2 = PK2(sab[j]), vv2 = PK2(vv[j]);
                S2[j][0] = FMA2(kk2[0], vv2, FMA2(bb2[0], sab2, MUL2(S2[j][0], ew2[0])));
                S2[j][1] = FMA2(kk2[1], vv2, FMA2(bb2[1], sab2, MUL2(S2[j][1], ew2[1])));
                po[j] = HADD2(FMA2(S2[j][1], rr2[1], MUL2(S2[j][0], rr2[0])));
                po[j] += __shfl_xor_sync(0xffffffffu, po[j], 1);
                po[j] += __shfl_xor_sync(0xffffffffu, po[j], 2);
            }
            #pragma unroll
            for (int j=0;j<4;j++)
                sab[j] = Dp[j] + sab[j]*bg.x + vv[j]*bg.y;

            if ((tid & 3) == 0){
                size_t ob = base4 + (size_t)(tb+u)*256;
                int p = cg >> 2;
                #pragma unroll
                for (int j=0;j<4;j++)
                    O4[ob + (size_t)(rowBase + rg + 8*j)*4 + p] = po[j];
            }
        }
    }
}

// ---------------- post: sum partials + groupnorm + bonus + gate ----------------
__global__ __launch_bounds__(256) void post_kernel(
    const float* __restrict__ O4, const float* __restrict__ RB, const float* __restrict__ K2p,
    const float* __restrict__ Vp, const float* __restrict__ G,
    const float* __restrict__ r_k, const float* __restrict__ gn_w, const float* __restrict__ gn_b,
    float* __restrict__ Z)
{
    int gw = (blockIdx.x*256 + threadIdx.x) >> 5;
    int lane = threadIdx.x & 31;
    int h = gw & 15, t = (gw >> 4) & 1023, b = gw >> 14;
    size_t bhtd = ((size_t)((b*HH + h)*TT + t))*64 + lane*2;
    int c = h*64 + lane*2;
    size_t btc = ((size_t)(b*TT + t))*CC + c;

    size_t b4 = ((size_t)(b*HH + h))*TT*256 + (size_t)t*256 + (size_t)lane*8;
    float4 pa = *(const float4*)&O4[b4];
    float4 pb = *(const float4*)&O4[b4 + 4];
    float2 o = make_float2(pa.x+pa.y+pa.z+pa.w, pb.x+pb.y+pb.z+pb.w);

    float sm = o.x + o.y;
    #pragma unroll
    for (int off=16; off>0; off>>=1) sm += __shfl_xor_sync(0xffffffffu, sm, off);
    float mean = sm * (1.f/64.f);
    float dx = o.x - mean, dy = o.y - mean;
    float vs = dx*dx + dy*dy;
    #pragma unroll
    for (int off=16; off>0; off>>=1) vs += __shfl_xor_sync(0xffffffffu, vs, off);
    float inv = rsqrtf(vs*(1.f/64.f) + GN_EPS);

    float2 r  = *(const float2*)&RB[btc];
    float2 k2 = *(const float2*)&K2p[bhtd];
    float2 v  = *(const float2*)&Vp[bhtd];
    float2 rk = *(const float2*)&r_k[c];
    float bs = r.x*k2.x*rk.x + r.y*k2.y*rk.y;
    #pragma unroll
    for (int off=16; off>0; off>>=1) bs += __shfl_xor_sync(0xffffffffu, bs, off);

    float2 g  = *(const float2*)&G[btc];
    float2 w  = *(const float2*)&gn_w[c];
    float2 bb = *(const float2*)&gn_b[c];
    float z0 = ((dx*inv)*w.x + bb.x + bs*v.x) * g.x;
    float z1 = ((dy*inv)*w.y + bb.y + bs*v.y) * g.y;
    *(float2*)&Z[btc] = make_float2(to_tf32(z0), to_tf32(z1));
}

// ---------------- driver ----------------
static inline GJob mkjob(const float* A, int lda, const float* B, int ldb, float* C, int ldc,
                         int N, int K, const float* bias, int mode, float scale, int ro,
                         int nrep, int ny){
    GJob j; j.A=A; j.B=B; j.C=C; j.bias=bias; j.lda=lda; j.ldb=ldb; j.ldc=ldc;
    j.N=N; j.K=K; j.mode=mode; j.scale=scale; j.round_out=ro; j.nrep=nrep; j.ny=ny; return j;
}

extern "C" void kernel_launch(void* const* d_in, const int* in_sizes, int n_in,
                              void* d_out, int out_size) {
    const float* x   = (const float*)d_in[0];
    const float* vfi = (const float*)d_in[1];
    const float* x_r = (const float*)d_in[2];
    const float* x_w = (const float*)d_in[3];
    const float* x_k = (const float*)d_in[4];
    const float* x_v = (const float*)d_in[5];
    const float* x_a = (const float*)d_in[6];
    const float* x_g = (const float*)d_in[7];
    const float* Wr  = (const float*)d_in[8];
    const float* Wk  = (const float*)d_in[9];
    const float* Wv  = (const float*)d_in[10];
    const float* Wo  = (const float*)d_in[11];
    const float* w0  = (const float*)d_in[12];
    const float* w1  = (const float*)d_in[13];
    const float* w2  = (const float*)d_in[14];
    const float* a0  = (const float*)d_in[15];
    const float* a1  = (const float*)d_in[16];
    const float* a2  = (const float*)d_in[17];
    const float* v0  = (const float*)d_in[18];
    const float* v1  = (const float*)d_in[19];
    const float* v2  = (const float*)d_in[20];
    const float* g1  = (const float*)d_in[21];
    const float* g2  = (const float*)d_in[22];
    const float* k_k = (const float*)d_in[23];
    const float* k_a = (const float*)d_in[24];
    const float* r_k = (const float*)d_in[25];
    const float* gnw = (const float*)d_in[26];
    const float* gnb = (const float*)d_in[27];
    float* out = (float*)d_out;

    float* S;
    cudaGetSymbolAddress((void**)&S, gScratch);

    const int SM128 = 3*(128+128)*32*4;   // 98304
    const int SM64  = 3*(128+64)*32*4;    // 73728
    cudaFuncSetAttribute(gemm_mma<128>, cudaFuncAttributeMaxDynamicSharedMemorySize, SM128);
    cudaFuncSetAttribute(gemm_mma<64>,  cudaFuncAttributeMaxDynamicSharedMemorySize, SM64);

    const int M = BB*TT;
    float* H = S + OHST;

    // 0: fused elementwise prep
    elem_prep<<<4096+2560+1152+4096, 256>>>(Wr, Wk, Wv, Wo, w1, a1, v1, g1, w2, a2, v2, g2,
                                            x_w, x_a, x_v, x_g, x, x_r, x_k, x_v, S);
    // 1: stage-1 split-K halves
    {
        GPack p{};
        p.j[0] = mkjob(S+OXC,      2048, S+OBU,      2048, S+OHLO, 320, 320, 1024, nullptr, 0, 1.f, 0, 1, 5);
        p.j[1] = mkjob(S+OXC+1024, 2048, S+OBU+1024, 2048, S+OHHI, 320, 320, 1024, nullptr, 0, 1.f, 0, 1, 5);
        gemm_mma<64><<<dim3(M/128,5,2), 256, SM64>>>(p);
    }
    // 2: H = act(Hlo + Hhi)
    hsum_act<<<1280, 256>>>(S+OHLO, S+OHHI, H);
    // 3: MERGED: R/K/V projections (z=0..2) + stage-2 low-rank (z=3..6)  <-- profiled (idx 3)
    {
        GPack p{};
        p.j[0] = mkjob(S+OXR, 1024, S+OWRr, 1024, S+ORB, 1024, 1024, 1024, nullptr, 0, 1.f, 0, 1, 8);
        p.j[1] = mkjob(S+OXK, 1024, S+OWKr, 1024, S+OKB, 1024, 1024, 1024, nullptr, 0, 1.f, 0, 1, 8);
        p.j[2] = mkjob(S+OXV, 1024, S+OWVr, 1024, S+OVB, 1024, 1024, 1024, nullptr, 0, 1.f, 0, 1, 8);
        p.j[3] = mkjob(H+0,   320, S+OW2T, 64,  S+OWL,  1024, 1024, 64,  w0, 2, LOG_DECAY, 0, 4, 2);
        p.j[4] = mkjob(H+64,  320, S+OA2T, 64,  S+OAB,  1024, 1024, 64,  a0, 2, 1.f, 0, 4, 2);
        p.j[5] = mkjob(H+128, 320, S+OV2T, 32,  S+OVMX, 1024, 1024, 32,  v0, 2, 1.f, 0, 4, 2);
        p.j[6] = mkjob(H+192, 320, S+OG2T, 128, S+OGB,  1024, 1024, 128, nullptr, 0, 1.f, 0, 4, 2);
        gemm_mma<128><<<dim3(M/128,8,7), 256, SM128>>>(p);
    }
    // 4: scan operand prep (fused look-ahead MA/BG)
    prep_kernel<<<(BB*TT*HH*32)/256, 256>>>(S+OKB, S+OAB, S+OVB, S+OWL, S+OVMX, vfi,
                                            k_k, k_a,
                                            S+OEW, S+OBBA, S+OKK2, S+OVVA, S+OMA, S+OBG);
    // 5: sequential scan v4b (8 steps/barrier, 32-stage ring)
    scan_kernel<<<BB*HH*2, 128>>>(S+OEW, S+OBBA, S+OMA, S+OKK2, S+ORB, S+OVVA, S+OBG, S+OO4);
    // 6: sum partials + groupnorm + bonus + gate
    post_kernel<<<(BB*TT*HH*32)/256, 256>>>(S+OO4, S+ORB, S+OKK2, S+OVVA, S+OGB,
                                            r_k, gnw, gnb, S+OZB);
    // 7: out = Z @ Wo^T
    {
        GPack p{};
        p.j[0] = mkjob(S+OZB, 1024, S+OWOr, 1024, out, 1024, 1024, 1024, nullptr, 0, 1.f, 0, 1, 8);
        gemm_mma<128><<<dim3(M/128,8,1), 256, SM128>>>(p);
    }
    // v_first passthrough
    if (out_size >= 2*NE){
        cudaMemcpyAsync(out + NE, vfi, (size_t)NE*sizeof(float), cudaMemcpyDeviceToDevice);
    }
}